// round 2
// baseline (speedup 1.0000x reference)
#include <cuda_runtime.h>
#include <math.h>

// ---------------------------------------------------------------------------
// DyHead-style MultiAttentionBlock, fp32 SIMT implementation.
// B=2, C=256, levels H = {128, 64, 32}, GN groups = 16.
// ---------------------------------------------------------------------------

constexpr int BN = 2;
constexpr int C  = 256;

// ---- scratch layout (floats) ----
constexpr size_t OFF_X0N   = 0;
constexpr size_t OFF_X1N   = OFF_X0N  + (size_t)BN*128*128*C;   // 8388608
constexpr size_t OFF_X2N   = OFF_X1N  + (size_t)BN*64*64*C;     // +2097152
constexpr size_t OFF_OFFB  = OFF_X2N  + (size_t)BN*32*32*C;     // +524288
constexpr size_t OFF_YMID  = OFF_OFFB + (size_t)BN*128*128*27;  // +884736
constexpr size_t OFF_YLOW  = OFF_YMID + (size_t)BN*C*128*128;
constexpr size_t OFF_YHIGH = OFF_YLOW + (size_t)BN*C*64*64;
constexpr size_t OFF_SUMF  = OFF_YHIGH+ (size_t)BN*C*64*64;
constexpr size_t OFF_W3MID = OFF_SUMF + (size_t)BN*C*128*128;
constexpr size_t OFF_W3LOW = OFF_W3MID + (size_t)9*256*256;
constexpr size_t OFF_W3HIGH= OFF_W3LOW + (size_t)9*256*256;
constexpr size_t OFF_W3OFF = OFF_W3HIGH+ (size_t)9*256*256;
constexpr size_t OFF_CHSUM = OFF_W3OFF + (size_t)9*256*32;
constexpr size_t OFF_CHSQ  = OFF_CHSUM + 512;
constexpr size_t OFF_GNM   = OFF_CHSQ  + 512;   // 3 branches * 32
constexpr size_t OFF_GNR   = OFF_GNM   + 96;
constexpr size_t OFF_SV    = OFF_GNR   + 96;    // 3 branches * 2 (padded)
constexpr size_t OFF_P2    = OFF_SV    + 8;
constexpr size_t OFF_COEF  = OFF_P2    + 512;
constexpr size_t SCRATCH_TOTAL = OFF_COEF + 2048;

__device__ __align__(256) float g_scratch[SCRATCH_TOTAL];

// ---------------------------------------------------------------------------
// Weight reorders: OIHW (O,C,3,3) -> [k][c][o]
// ---------------------------------------------------------------------------
__global__ void reorder_w_kernel(const float* __restrict__ w, size_t out_o) {
    int idx = blockIdx.x * 256 + threadIdx.x;       // < 9*256*256
    int o = idx & 255, c = (idx >> 8) & 255, k = idx >> 16;
    g_scratch[out_o + idx] = w[(o * 256 + c) * 9 + k];
}

__global__ void reorder_woff_kernel(const float* __restrict__ w, size_t out_o) {
    int idx = blockIdx.x * 256 + threadIdx.x;       // < 9*256*32
    int o = idx & 31, c = (idx >> 5) & 255, k = idx >> 13;
    g_scratch[out_o + idx] = (o < 27) ? w[(o * 256 + c) * 9 + k] : 0.f;
}

// ---------------------------------------------------------------------------
// NCHW -> NHWC transpose.  in: [b][C][HW]  out: [b][HW][C]
// ---------------------------------------------------------------------------
__global__ void transpose_kernel(const float* __restrict__ in, size_t out_o, int HW) {
    __shared__ float t[32][33];
    int b = blockIdx.z;
    int hw0 = blockIdx.x * 32, c0 = blockIdx.y * 32;
    int tx = threadIdx.x, ty = threadIdx.y;  // 32 x 8
    #pragma unroll
    for (int i = 0; i < 32; i += 8)
        t[ty + i][tx] = in[((size_t)b * C + c0 + ty + i) * HW + hw0 + tx];
    __syncthreads();
    #pragma unroll
    for (int i = 0; i < 32; i += 8)
        g_scratch[out_o + ((size_t)b * HW + hw0 + ty + i) * C + c0 + tx] = t[tx][ty + i];
}

// ---------------------------------------------------------------------------
// Offset conv: 3x3, 256 -> 27 (padded to 32), zero-pad.
// Output layout [b][h][w][27], channels 18..26 sigmoid'ed (mask).
// Block: 128 px tile, 256 threads (o = tid&31, pxg = tid>>5).
// ---------------------------------------------------------------------------
__global__ __launch_bounds__(256) void offconv_kernel(
    size_t xn_o, int H, int W,
    size_t w3_o, const float* __restrict__ bias, size_t out_o)
{
    int b = blockIdx.y, tile = blockIdx.x, tid = threadIdx.x;
    __shared__ float As[16][128];
    __shared__ float Bs[16][32];
    int o = tid & 31, pxg = tid >> 5;
    const float* xn = g_scratch + xn_o;

    float acc[16];
    #pragma unroll
    for (int j = 0; j < 16; ++j) acc[j] = 0.f;

    for (int k = 0; k < 9; ++k) {
        int dy = k / 3 - 1, dx = k % 3 - 1;
        for (int c0 = 0; c0 < 256; c0 += 16) {
            __syncthreads();
            // A tile: 128 px x 16 c (im2col with zero pad). 512 float4s.
            #pragma unroll
            for (int i = 0; i < 2; ++i) {
                int e4 = i * 256 + tid;
                int px = e4 >> 2, cq = e4 & 3;
                int p = tile * 128 + px;
                int h = p / W, w = p - h * W;
                int y = h + dy, x = w + dx;
                float4 v = make_float4(0.f, 0.f, 0.f, 0.f);
                if (y >= 0 && y < H && x >= 0 && x < W)
                    v = *(const float4*)(xn + ((size_t)(b * H + y) * W + x) * 256 + c0 + cq * 4);
                As[cq * 4 + 0][px] = v.x;
                As[cq * 4 + 1][px] = v.y;
                As[cq * 4 + 2][px] = v.z;
                As[cq * 4 + 3][px] = v.w;
            }
            // B tile: 16 c x 32 o
            #pragma unroll
            for (int i = 0; i < 2; ++i) {
                int e = i * 256 + tid;
                int cc = e >> 5, oo = e & 31;
                Bs[cc][oo] = g_scratch[w3_o + ((size_t)(k * 256 + c0 + cc) << 5) + oo];
            }
            __syncthreads();
            #pragma unroll
            for (int cc = 0; cc < 16; ++cc) {
                float bb = Bs[cc][o];
                float4 a0 = *(const float4*)&As[cc][pxg * 16 + 0];
                float4 a1 = *(const float4*)&As[cc][pxg * 16 + 4];
                float4 a2 = *(const float4*)&As[cc][pxg * 16 + 8];
                float4 a3 = *(const float4*)&As[cc][pxg * 16 + 12];
                acc[0]  += a0.x * bb; acc[1]  += a0.y * bb; acc[2]  += a0.z * bb; acc[3]  += a0.w * bb;
                acc[4]  += a1.x * bb; acc[5]  += a1.y * bb; acc[6]  += a1.z * bb; acc[7]  += a1.w * bb;
                acc[8]  += a2.x * bb; acc[9]  += a2.y * bb; acc[10] += a2.z * bb; acc[11] += a2.w * bb;
                acc[12] += a3.x * bb; acc[13] += a3.y * bb; acc[14] += a3.z * bb; acc[15] += a3.w * bb;
            }
        }
    }
    if (o < 27) {
        float bv = bias[o];
        #pragma unroll
        for (int j = 0; j < 16; ++j) {
            int p = tile * 128 + pxg * 16 + j;
            int h = p / W, w = p - h * W;
            float v = acc[j] + bv;
            if (o >= 18) v = 1.f / (1.f + expf(-v));
            g_scratch[out_o + ((size_t)(b * H + h) * W + w) * 27 + o] = v;
        }
    }
}

// ---------------------------------------------------------------------------
// Modulated deformable conv as fused gather + GEMM.
// out[b, o, px] = sum_{k,c} mask*bilinear(x)[b,c,k,px] * W3[k][c][o]
// Block: 32 px x 256 o, 256 threads, acc 4px x 8o per thread.
// ---------------------------------------------------------------------------
__global__ __launch_bounds__(256) void mdconv_kernel(
    size_t xn_o, int Hi, int Wi,
    size_t off_o, int offH, int offW, int offmul,
    int stride, size_t w3_o,
    size_t y_o, int Wo, int HWo)
{
    int b = blockIdx.y;
    int tile = blockIdx.x;
    int tid = threadIdx.x;

    __shared__ float As[16][32];
    __shared__ float Bs[16][256];
    __shared__ int   sbase[4][32];
    __shared__ float swt[4][32];

    const float* xn = g_scratch + xn_o;

    float acc[4][8];
    #pragma unroll
    for (int i = 0; i < 4; ++i)
        #pragma unroll
        for (int j = 0; j < 8; ++j) acc[i][j] = 0.f;

    int pxq = tid & 7;     // 8 quads of 4 px
    int oct = tid >> 3;    // 32 octs of 8 o
    int px0 = pxq * 4;
    int o0  = oct * 8;
    int gpx = tid >> 2;    // gather: px (valid for tid<128)
    int gcq = tid & 3;     // gather: c-quad

    for (int k = 0; k < 9; ++k) {
        __syncthreads();
        if (tid < 32) {
            int p = tile * 32 + tid;
            int h = p / Wo, w = p - h * Wo;
            size_t ob = off_o + ((size_t)(b * offH + h * offmul) * offW + w * offmul) * 27;
            float oy = g_scratch[ob + 2 * k];
            float ox = g_scratch[ob + 2 * k + 1];
            float m  = g_scratch[ob + 18 + k];
            float py  = (float)(h * stride - 1 + k / 3) + oy;
            float pxx = (float)(w * stride - 1 + k % 3) + ox;
            float fy = floorf(py), fx = floorf(pxx);
            int y0 = (int)fy, x0 = (int)fx;
            float wy = py - fy, wx = pxx - fx;
            int y1 = y0 + 1, x1 = x0 + 1;
            float vy0 = (y0 >= 0 && y0 < Hi) ? 1.f : 0.f;
            float vy1 = (y1 >= 0 && y1 < Hi) ? 1.f : 0.f;
            float vx0 = (x0 >= 0 && x0 < Wi) ? 1.f : 0.f;
            float vx1 = (x1 >= 0 && x1 < Wi) ? 1.f : 0.f;
            int y0c = min(max(y0, 0), Hi - 1), y1c = min(max(y1, 0), Hi - 1);
            int x0c = min(max(x0, 0), Wi - 1), x1c = min(max(x1, 0), Wi - 1);
            swt[0][tid] = (1.f - wy) * (1.f - wx) * m * vy0 * vx0;
            swt[1][tid] = (1.f - wy) * wx * m * vy0 * vx1;
            swt[2][tid] = wy * (1.f - wx) * m * vy1 * vx0;
            swt[3][tid] = wy * wx * m * vy1 * vx1;
            sbase[0][tid] = ((b * Hi + y0c) * Wi + x0c) * 256;
            sbase[1][tid] = ((b * Hi + y0c) * Wi + x1c) * 256;
            sbase[2][tid] = ((b * Hi + y1c) * Wi + x0c) * 256;
            sbase[3][tid] = ((b * Hi + y1c) * Wi + x1c) * 256;
        }
        __syncthreads();

        float w00 = 0.f, w01 = 0.f, w10 = 0.f, w11 = 0.f;
        int b00 = 0, b01 = 0, b10 = 0, b11 = 0;
        if (tid < 128) {
            w00 = swt[0][gpx]; w01 = swt[1][gpx]; w10 = swt[2][gpx]; w11 = swt[3][gpx];
            b00 = sbase[0][gpx]; b01 = sbase[1][gpx]; b10 = sbase[2][gpx]; b11 = sbase[3][gpx];
        }

        for (int c0 = 0; c0 < 256; c0 += 16) {
            if (tid < 128) {
                int cofs = c0 + gcq * 4;
                float4 v00 = *(const float4*)(xn + b00 + cofs);
                float4 v01 = *(const float4*)(xn + b01 + cofs);
                float4 v10 = *(const float4*)(xn + b10 + cofs);
                float4 v11 = *(const float4*)(xn + b11 + cofs);
                As[gcq * 4 + 0][gpx] = w00 * v00.x + w01 * v01.x + w10 * v10.x + w11 * v11.x;
                As[gcq * 4 + 1][gpx] = w00 * v00.y + w01 * v01.y + w10 * v10.y + w11 * v11.y;
                As[gcq * 4 + 2][gpx] = w00 * v00.z + w01 * v01.z + w10 * v10.z + w11 * v11.z;
                As[gcq * 4 + 3][gpx] = w00 * v00.w + w01 * v01.w + w10 * v10.w + w11 * v11.w;
            }
            #pragma unroll
            for (int i = 0; i < 4; ++i) {
                int e4 = i * 256 + tid;           // 0..1023
                int o4 = (e4 & 63) * 4;
                int cc = e4 >> 6;
                *(float4*)&Bs[cc][o4] =
                    *(const float4*)&g_scratch[w3_o + (((size_t)(k << 8) + c0 + cc) << 8) + o4];
            }
            __syncthreads();
            #pragma unroll
            for (int cc = 0; cc < 16; ++cc) {
                float4 a   = *(const float4*)&As[cc][px0];
                float4 bb0 = *(const float4*)&Bs[cc][o0];
                float4 bb1 = *(const float4*)&Bs[cc][o0 + 4];
                acc[0][0] += a.x * bb0.x; acc[0][1] += a.x * bb0.y; acc[0][2] += a.x * bb0.z; acc[0][3] += a.x * bb0.w;
                acc[0][4] += a.x * bb1.x; acc[0][5] += a.x * bb1.y; acc[0][6] += a.x * bb1.z; acc[0][7] += a.x * bb1.w;
                acc[1][0] += a.y * bb0.x; acc[1][1] += a.y * bb0.y; acc[1][2] += a.y * bb0.z; acc[1][3] += a.y * bb0.w;
                acc[1][4] += a.y * bb1.x; acc[1][5] += a.y * bb1.y; acc[1][6] += a.y * bb1.z; acc[1][7] += a.y * bb1.w;
                acc[2][0] += a.z * bb0.x; acc[2][1] += a.z * bb0.y; acc[2][2] += a.z * bb0.z; acc[2][3] += a.z * bb0.w;
                acc[2][4] += a.z * bb1.x; acc[2][5] += a.z * bb1.y; acc[2][6] += a.z * bb1.z; acc[2][7] += a.z * bb1.w;
                acc[3][0] += a.w * bb0.x; acc[3][1] += a.w * bb0.y; acc[3][2] += a.w * bb0.z; acc[3][3] += a.w * bb0.w;
                acc[3][4] += a.w * bb1.x; acc[3][5] += a.w * bb1.y; acc[3][6] += a.w * bb1.z; acc[3][7] += a.w * bb1.w;
            }
            __syncthreads();
        }
    }
    int pbase = tile * 32 + px0;
    #pragma unroll
    for (int j = 0; j < 8; ++j) {
        int o = o0 + j;
        float4 v = make_float4(acc[0][j], acc[1][j], acc[2][j], acc[3][j]);
        *(float4*)&g_scratch[y_o + ((size_t)(b * 256 + o)) * HWo + pbase] = v;
    }
}

// ---------------------------------------------------------------------------
// Per-(b,c) spatial sum + sumsq over HW (NCHW input in scratch).
// ---------------------------------------------------------------------------
__global__ void chan_stats_kernel(size_t y_o, int HW, size_t sum_o, size_t sq_o) {
    int c = blockIdx.x, b = blockIdx.y, tid = threadIdx.x;
    const float4* p = (const float4*)(g_scratch + y_o + ((size_t)(b * 256 + c)) * HW);
    float s = 0.f, q = 0.f;
    for (int i = tid; i < (HW >> 2); i += 256) {
        float4 v = p[i];
        s += v.x + v.y + v.z + v.w;
        q += v.x * v.x + v.y * v.y + v.z * v.z + v.w * v.w;
    }
    #pragma unroll
    for (int o = 16; o; o >>= 1) {
        s += __shfl_down_sync(0xffffffffu, s, o);
        q += __shfl_down_sync(0xffffffffu, q, o);
    }
    __shared__ float rs[8], rq[8];
    if ((tid & 31) == 0) { rs[tid >> 5] = s; rq[tid >> 5] = q; }
    __syncthreads();
    if (tid == 0) {
        float ts = 0.f, tq = 0.f;
        #pragma unroll
        for (int i = 0; i < 8; ++i) { ts += rs[i]; tq += rq[i]; }
        g_scratch[sum_o + b * 256 + c] = ts;
        g_scratch[sq_o + b * 256 + c] = tq;
    }
}

// ---------------------------------------------------------------------------
// GN finalize: per-(b,g) mean/rstd, plus scale-attn scalar s[b] (analytic pool).
// ---------------------------------------------------------------------------
__global__ void gn_finalize_kernel(
    size_t sum_o, size_t sq_o,
    const float* __restrict__ gamma, const float* __restrict__ beta,
    const float* __restrict__ w_sa, const float* __restrict__ b_sa,
    float inv_hw, float inv_cnt,
    size_t gnm_o, size_t gnr_o, size_t sv_o)
{
    int b = blockIdx.x, t = threadIdx.x;  // 256
    __shared__ float ss[256], qq[256], gm[16], gr[16], red[256];
    ss[t] = g_scratch[sum_o + b * 256 + t];
    qq[t] = g_scratch[sq_o + b * 256 + t];
    __syncthreads();
    if (t < 16) {
        float S = 0.f, Q = 0.f;
        #pragma unroll
        for (int j = 0; j < 16; ++j) { S += ss[t * 16 + j]; Q += qq[t * 16 + j]; }
        float mean = S * inv_cnt;
        float var = Q * inv_cnt - mean * mean;
        float r = rsqrtf(var + 1e-5f);
        gm[t] = mean; gr[t] = r;
        g_scratch[gnm_o + b * 16 + t] = mean;
        g_scratch[gnr_o + b * 16 + t] = r;
    }
    __syncthreads();
    int g = t >> 4;
    float p = gamma[t] * (ss[t] * inv_hw - gm[g]) * gr[g] + beta[t];
    red[t] = p * w_sa[t];
    __syncthreads();
    for (int off = 128; off; off >>= 1) {
        if (t < off) red[t] += red[t + off];
        __syncthreads();
    }
    if (t == 0) {
        float x = fmaxf(red[0] + b_sa[0], 0.f);
        g_scratch[sv_o + b] = fminf(x + 3.f, 6.f) * (1.f / 6.f);
    }
}

__global__ void zero_kernel(size_t o, int n) {
    int i = blockIdx.x * 256 + threadIdx.x;
    if (i < n) g_scratch[o + i] = 0.f;
}

// ---------------------------------------------------------------------------
// Combine branches: GN affine + scale-attn weight + bilinear upsample (high),
// divide by n, write sum_feat, accumulate per-(b,c) pooled sums.
// grid: (HW/256, C, B)
// ---------------------------------------------------------------------------
__global__ void combine_kernel(
    size_t ymid_o, size_t ylow_o, size_t yhigh_o,
    int hasLow, int hasHigh, int W, int HW, int Hh, int Wh, float ry, float rx,
    size_t gnm_o, size_t gnr_o, size_t sv_o,
    const float* __restrict__ gw_mid, const float* __restrict__ gb_mid,
    const float* __restrict__ gw_low, const float* __restrict__ gb_low,
    const float* __restrict__ gw_high, const float* __restrict__ gb_high,
    float inv_n, size_t sumf_o, size_t p2_o)
{
    int b = blockIdx.z, c = blockIdx.y;
    int px = blockIdx.x * 256 + threadIdx.x;
    int g = c >> 4;
    int gi = b * 16 + g;
    size_t base = ((size_t)(b * 256 + c)) * HW;

    float v = g_scratch[sv_o + b] *
              (gw_mid[c] * (g_scratch[ymid_o + base + px] - g_scratch[gnm_o + gi]) * g_scratch[gnr_o + gi] + gb_mid[c]);
    if (hasLow)
        v += g_scratch[sv_o + 2 + b] *
             (gw_low[c] * (g_scratch[ylow_o + base + px] - g_scratch[gnm_o + 32 + gi]) * g_scratch[gnr_o + 32 + gi] + gb_low[c]);
    if (hasHigh) {
        int h = px / W, w = px - h * W;
        float sy = h * ry, sx = w * rx;
        int yl = (int)sy; int yh2 = min(yl + 1, Hh - 1);
        int xl = (int)sx; int xh = min(xl + 1, Wh - 1);
        float wy = sy - (float)yl, wx = sx - (float)xl;
        const float* hp = g_scratch + yhigh_o + ((size_t)(b * 256 + c)) * Hh * Wh;
        float t0 = hp[yl * Wh + xl] * (1.f - wx) + hp[yl * Wh + xh] * wx;
        float t1 = hp[yh2 * Wh + xl] * (1.f - wx) + hp[yh2 * Wh + xh] * wx;
        float raw = t0 * (1.f - wy) + t1 * wy;
        v += g_scratch[sv_o + 4 + b] *
             (gw_high[c] * (raw - g_scratch[gnm_o + 64 + gi]) * g_scratch[gnr_o + 64 + gi] + gb_high[c]);
    }
    v *= inv_n;
    g_scratch[sumf_o + base + px] = v;

    float r = v;
    #pragma unroll
    for (int o = 16; o; o >>= 1) r += __shfl_down_sync(0xffffffffu, r, o);
    __shared__ float wsum[8];
    if ((threadIdx.x & 31) == 0) wsum[threadIdx.x >> 5] = r;
    __syncthreads();
    if (threadIdx.x == 0) {
        float tt = 0.f;
        #pragma unroll
        for (int i = 0; i < 8; ++i) tt += wsum[i];
        atomicAdd(&g_scratch[p2_o + b * 256 + c], tt);
    }
}

// ---------------------------------------------------------------------------
// DyReLU coefficients: p -> relu(p@w1^T+b1) -> hsig(.@w2^T+b2) - 0.5
// grid (B), block 1024.
// ---------------------------------------------------------------------------
__global__ void dycoef_kernel(size_t p2_o, float inv_hw,
    const float* __restrict__ w1, const float* __restrict__ b1,
    const float* __restrict__ w2, const float* __restrict__ b2,
    size_t coef_o)
{
    int b = blockIdx.x, t = threadIdx.x;  // 1024
    __shared__ float pm[256], hb[64];
    if (t < 256) pm[t] = g_scratch[p2_o + b * 256 + t] * inv_hw;
    __syncthreads();
    if (t < 64) {
        float a = b1[t];
        for (int cx = 0; cx < 256; ++cx) a += pm[cx] * w1[t * 256 + cx];
        hb[t] = fmaxf(a, 0.f);
    }
    __syncthreads();
    float a = b2[t];
    #pragma unroll
    for (int i = 0; i < 64; ++i) a += hb[i] * w2[t * 64 + i];
    float hs = fminf(fmaxf(a + 3.f, 0.f), 6.f) * (1.f / 6.f);
    g_scratch[coef_o + b * 1024 + t] = hs - 0.5f;
}

// ---------------------------------------------------------------------------
// Apply DyReLU, write final output.
// ---------------------------------------------------------------------------
__global__ void dyrelu_kernel(size_t sumf_o, size_t coef_o, int HW, float* __restrict__ outp, int CHW) {
    int idx = blockIdx.x * 256 + threadIdx.x;
    int b = idx / CHW;
    int c = (idx - b * CHW) / HW;
    const float* cf = g_scratch + coef_o + b * 1024;
    float x = g_scratch[sumf_o + idx];
    float a1 = cf[c] * 2.f + 1.f, bb1 = cf[256 + c];
    float a2 = cf[512 + c] * 2.f, bb2 = cf[768 + c];
    outp[idx] = fmaxf(x * a1 + bb1, x * a2 + bb2);
}

// ---------------------------------------------------------------------------
// Host orchestration
// ---------------------------------------------------------------------------
extern "C" void kernel_launch(void* const* d_in, const int* in_sizes, int n_in,
                              void* d_out, int out_size) {
    (void)in_sizes; (void)n_in; (void)out_size;
    const float* x0     = (const float*)d_in[0];
    const float* x1     = (const float*)d_in[1];
    const float* x2     = (const float*)d_in[2];
    const float* w_off  = (const float*)d_in[3];
    const float* b_off  = (const float*)d_in[4];
    const float* w_mid  = (const float*)d_in[5];
    const float* g_mid  = (const float*)d_in[6];
    const float* be_mid = (const float*)d_in[7];
    const float* w_low  = (const float*)d_in[8];
    const float* g_low  = (const float*)d_in[9];
    const float* be_low = (const float*)d_in[10];
    const float* w_high = (const float*)d_in[11];
    const float* g_high = (const float*)d_in[12];
    const float* be_high= (const float*)d_in[13];
    const float* w_sa   = (const float*)d_in[14];
    const float* b_sa   = (const float*)d_in[15];
    const float* w_dy1  = (const float*)d_in[16];
    const float* b_dy1  = (const float*)d_in[17];
    const float* w_dy2  = (const float*)d_in[18];
    const float* b_dy2  = (const float*)d_in[19];
    float* out = (float*)d_out;

    // weight reorders
    reorder_w_kernel<<<2304, 256>>>(w_mid,  OFF_W3MID);
    reorder_w_kernel<<<2304, 256>>>(w_low,  OFF_W3LOW);
    reorder_w_kernel<<<2304, 256>>>(w_high, OFF_W3HIGH);
    reorder_woff_kernel<<<288, 256>>>(w_off, OFF_W3OFF);

    // NCHW -> NHWC transposes
    {
        dim3 blk(32, 8);
        transpose_kernel<<<dim3(128 * 128 / 32, 8, 2), blk>>>(x0, OFF_X0N, 128 * 128);
        transpose_kernel<<<dim3(64 * 64 / 32, 8, 2), blk>>>(x1, OFF_X1N, 64 * 64);
        transpose_kernel<<<dim3(32 * 32 / 32, 8, 2), blk>>>(x2, OFF_X2N, 32 * 32);
    }

    const int Hs[3] = {128, 64, 32};
    const size_t xn_offs[3] = {OFF_X0N, OFF_X1N, OFF_X2N};
    size_t outoff = 0;

    for (int l = 0; l < 3; ++l) {
        int H = Hs[l], HW = H * H;
        int hasLow = (l > 0), hasHigh = (l < 2);
        int nbr = 1 + hasLow + hasHigh;

        // offset conv
        offconv_kernel<<<dim3(HW / 128, 2), 256>>>(xn_offs[l], H, H, OFF_W3OFF, b_off, OFF_OFFB);

        // mid branch
        mdconv_kernel<<<dim3(HW / 32, 2), 256>>>(xn_offs[l], H, H, OFF_OFFB, H, H, 1, 1,
                                                 OFF_W3MID, OFF_YMID, H, HW);
        chan_stats_kernel<<<dim3(256, 2), 256>>>(OFF_YMID, HW, OFF_CHSUM, OFF_CHSQ);
        gn_finalize_kernel<<<2, 256>>>(OFF_CHSUM, OFF_CHSQ, g_mid, be_mid, w_sa, b_sa,
                                       1.f / HW, 1.f / (16.f * HW),
                                       OFF_GNM, OFF_GNR, OFF_SV);
        // low branch
        if (hasLow) {
            int Hi = Hs[l - 1];
            mdconv_kernel<<<dim3(HW / 32, 2), 256>>>(xn_offs[l - 1], Hi, Hi, OFF_OFFB, H, H, 1, 2,
                                                     OFF_W3LOW, OFF_YLOW, H, HW);
            chan_stats_kernel<<<dim3(256, 2), 256>>>(OFF_YLOW, HW, OFF_CHSUM, OFF_CHSQ);
            gn_finalize_kernel<<<2, 256>>>(OFF_CHSUM, OFF_CHSQ, g_low, be_low, w_sa, b_sa,
                                           1.f / HW, 1.f / (16.f * HW),
                                           OFF_GNM + 32, OFF_GNR + 32, OFF_SV + 2);
        }
        // high branch
        int Hh = H / 2, HWh = Hh * Hh;
        if (hasHigh) {
            mdconv_kernel<<<dim3(HWh / 32, 2), 256>>>(xn_offs[l + 1], Hh, Hh, OFF_OFFB, H, H, 2, 1,
                                                      OFF_W3HIGH, OFF_YHIGH, Hh, HWh);
            chan_stats_kernel<<<dim3(256, 2), 256>>>(OFF_YHIGH, HWh, OFF_CHSUM, OFF_CHSQ);
            gn_finalize_kernel<<<2, 256>>>(OFF_CHSUM, OFF_CHSQ, g_high, be_high, w_sa, b_sa,
                                           1.f / HWh, 1.f / (16.f * HWh),
                                           OFF_GNM + 64, OFF_GNR + 64, OFF_SV + 4);
        }

        zero_kernel<<<2, 256>>>(OFF_P2, 512);
        float ry = (float)(Hh - 1) / (float)(H - 1);
        combine_kernel<<<dim3(HW / 256, 256, 2), 256>>>(
            OFF_YMID, OFF_YLOW, OFF_YHIGH, hasLow, hasHigh,
            H, HW, Hh, Hh, ry, ry,
            OFF_GNM, OFF_GNR, OFF_SV,
            g_mid, be_mid, g_low, be_low, g_high, be_high,
            1.f / (float)nbr, OFF_SUMF, OFF_P2);

        dycoef_kernel<<<2, 1024>>>(OFF_P2, 1.f / HW, w_dy1, b_dy1, w_dy2, b_dy2, OFF_COEF);

        int total = 2 * 256 * HW;
        dyrelu_kernel<<<total / 256, 256>>>(OFF_SUMF, OFF_COEF, HW, out + outoff, 256 * HW);
        outoff += (size_t)total;
    }
}

// round 3
// speedup vs baseline: 1.3975x; 1.3975x over previous
#include <cuda_runtime.h>
#include <math.h>
#include <stdint.h>

// ---------------------------------------------------------------------------
// DyHead-style MultiAttentionBlock. fp32 + TF32 tensor-core mdconv.
// B=2, C=256, levels H = {128, 64, 32}, GN groups = 16.
// ---------------------------------------------------------------------------

constexpr int BN = 2;
constexpr int C  = 256;

// ---- scratch layout (floats) ----
constexpr size_t OFF_X0N   = 0;
constexpr size_t OFF_X1N   = OFF_X0N  + (size_t)BN*128*128*C;
constexpr size_t OFF_X2N   = OFF_X1N  + (size_t)BN*64*64*C;
constexpr size_t OFF_OFFB  = OFF_X2N  + (size_t)BN*32*32*C;
constexpr size_t OFF_YMID  = OFF_OFFB + (size_t)BN*128*128*27;
constexpr size_t OFF_YLOW  = OFF_YMID + (size_t)BN*C*128*128;
constexpr size_t OFF_YHIGH = OFF_YLOW + (size_t)BN*C*64*64;
constexpr size_t OFF_SUMF  = OFF_YHIGH+ (size_t)BN*C*64*64;
constexpr size_t OFF_W3MID = OFF_SUMF + (size_t)BN*C*128*128;
constexpr size_t OFF_W3LOW = OFF_W3MID + (size_t)9*256*256;
constexpr size_t OFF_W3HIGH= OFF_W3LOW + (size_t)9*256*256;
constexpr size_t OFF_W3OFF = OFF_W3HIGH+ (size_t)9*256*256;
constexpr size_t OFF_CHSUM = OFF_W3OFF + (size_t)9*256*32;
constexpr size_t OFF_CHSQ  = OFF_CHSUM + 512;
constexpr size_t OFF_GNM   = OFF_CHSQ  + 512;
constexpr size_t OFF_GNR   = OFF_GNM   + 96;
constexpr size_t OFF_SV    = OFF_GNR   + 96;
constexpr size_t OFF_P2    = OFF_SV    + 8;
constexpr size_t OFF_COEF  = OFF_P2    + 512;
constexpr size_t SCRATCH_TOTAL = OFF_COEF + 2048;

__device__ __align__(256) float g_scratch[SCRATCH_TOTAL];

__device__ __forceinline__ float f2tf32(float f) {
    uint32_t r;
    asm("cvt.rna.tf32.f32 %0, %1;" : "=r"(r) : "f"(f));
    return __uint_as_float(r);
}

__device__ __forceinline__ void mma_tf32(float* d, const uint32_t* a, uint32_t b0, uint32_t b1) {
    asm volatile(
        "mma.sync.aligned.m16n8k8.row.col.f32.tf32.tf32.f32 "
        "{%0,%1,%2,%3},{%4,%5,%6,%7},{%8,%9},{%0,%1,%2,%3};\n"
        : "+f"(d[0]), "+f"(d[1]), "+f"(d[2]), "+f"(d[3])
        : "r"(a[0]), "r"(a[1]), "r"(a[2]), "r"(a[3]), "r"(b0), "r"(b1));
}

// ---------------------------------------------------------------------------
// Weight reorders: OIHW (O,C,3,3) -> [k][c][o], tf32-rounded for MMA weights.
// ---------------------------------------------------------------------------
__global__ void reorder_w_tf32_kernel(const float* __restrict__ w, size_t out_o) {
    int idx = blockIdx.x * 256 + threadIdx.x;       // < 9*256*256
    int o = idx & 255, c = (idx >> 8) & 255, k = idx >> 16;
    g_scratch[out_o + idx] = f2tf32(w[(o * 256 + c) * 9 + k]);
}

__global__ void reorder_woff_kernel(const float* __restrict__ w, size_t out_o) {
    int idx = blockIdx.x * 256 + threadIdx.x;       // < 9*256*32
    int o = idx & 31, c = (idx >> 5) & 255, k = idx >> 13;
    g_scratch[out_o + idx] = (o < 27) ? w[(o * 256 + c) * 9 + k] : 0.f;
}

// ---------------------------------------------------------------------------
// NCHW -> NHWC transpose.  in: [b][C][HW]  out: [b][HW][C]
// ---------------------------------------------------------------------------
__global__ void transpose_kernel(const float* __restrict__ in, size_t out_o, int HW) {
    __shared__ float t[32][33];
    int b = blockIdx.z;
    int hw0 = blockIdx.x * 32, c0 = blockIdx.y * 32;
    int tx = threadIdx.x, ty = threadIdx.y;  // 32 x 8
    #pragma unroll
    for (int i = 0; i < 32; i += 8)
        t[ty + i][tx] = in[((size_t)b * C + c0 + ty + i) * HW + hw0 + tx];
    __syncthreads();
    #pragma unroll
    for (int i = 0; i < 32; i += 8)
        g_scratch[out_o + ((size_t)b * HW + hw0 + ty + i) * C + c0 + tx] = t[tx][ty + i];
}

// ---------------------------------------------------------------------------
// Offset conv: 3x3, 256 -> 27 (padded to 32), zero-pad. fp32 SIMT.
// Output layout [b][h][w][27], channels 18..26 sigmoid'ed (mask).
// ---------------------------------------------------------------------------
__global__ __launch_bounds__(256) void offconv_kernel(
    size_t xn_o, int H, int W,
    size_t w3_o, const float* __restrict__ bias, size_t out_o)
{
    int b = blockIdx.y, tile = blockIdx.x, tid = threadIdx.x;
    __shared__ float As[16][128];
    __shared__ float Bs[16][32];
    int o = tid & 31, pxg = tid >> 5;
    const float* xn = g_scratch + xn_o;

    float acc[16];
    #pragma unroll
    for (int j = 0; j < 16; ++j) acc[j] = 0.f;

    for (int k = 0; k < 9; ++k) {
        int dy = k / 3 - 1, dx = k % 3 - 1;
        for (int c0 = 0; c0 < 256; c0 += 16) {
            __syncthreads();
            #pragma unroll
            for (int i = 0; i < 2; ++i) {
                int e4 = i * 256 + tid;
                int px = e4 >> 2, cq = e4 & 3;
                int p = tile * 128 + px;
                int h = p / W, w = p - h * W;
                int y = h + dy, x = w + dx;
                float4 v = make_float4(0.f, 0.f, 0.f, 0.f);
                if (y >= 0 && y < H && x >= 0 && x < W)
                    v = *(const float4*)(xn + ((size_t)(b * H + y) * W + x) * 256 + c0 + cq * 4);
                As[cq * 4 + 0][px] = v.x;
                As[cq * 4 + 1][px] = v.y;
                As[cq * 4 + 2][px] = v.z;
                As[cq * 4 + 3][px] = v.w;
            }
            #pragma unroll
            for (int i = 0; i < 2; ++i) {
                int e = i * 256 + tid;
                int cc = e >> 5, oo = e & 31;
                Bs[cc][oo] = g_scratch[w3_o + ((size_t)(k * 256 + c0 + cc) << 5) + oo];
            }
            __syncthreads();
            #pragma unroll
            for (int cc = 0; cc < 16; ++cc) {
                float bb = Bs[cc][o];
                float4 a0 = *(const float4*)&As[cc][pxg * 16 + 0];
                float4 a1 = *(const float4*)&As[cc][pxg * 16 + 4];
                float4 a2 = *(const float4*)&As[cc][pxg * 16 + 8];
                float4 a3 = *(const float4*)&As[cc][pxg * 16 + 12];
                acc[0]  += a0.x * bb; acc[1]  += a0.y * bb; acc[2]  += a0.z * bb; acc[3]  += a0.w * bb;
                acc[4]  += a1.x * bb; acc[5]  += a1.y * bb; acc[6]  += a1.z * bb; acc[7]  += a1.w * bb;
                acc[8]  += a2.x * bb; acc[9]  += a2.y * bb; acc[10] += a2.z * bb; acc[11] += a2.w * bb;
                acc[12] += a3.x * bb; acc[13] += a3.y * bb; acc[14] += a3.z * bb; acc[15] += a3.w * bb;
            }
        }
    }
    if (o < 27) {
        float bv = bias[o];
        #pragma unroll
        for (int j = 0; j < 16; ++j) {
            int p = tile * 128 + pxg * 16 + j;
            int h = p / W, w = p - h * W;
            float v = acc[j] + bv;
            if (o >= 18) v = 1.f / (1.f + expf(-v));
            g_scratch[out_o + ((size_t)(b * H + h) * W + w) * 27 + o] = v;
        }
    }
}

// ---------------------------------------------------------------------------
// Modulated deformable conv: fused bilinear gather + TF32 tensor-core GEMM.
// Block: 64 px x 256 o, 256 threads (8 warps = 2M x 4N), K-chunks of 32.
// Each warp: 32px x 64o via m16n8k8 (2 m-tiles x 8 n-tiles).
// ---------------------------------------------------------------------------
__global__ __launch_bounds__(256, 2) void mdconv_mma_kernel(
    size_t xn_o, int Hi, int Wi,
    size_t off_o, int offH, int offW, int offmul,
    int stride, size_t w3_o,
    size_t y_o, int HWo, int Wo)
{
    __shared__ float As[32][72];      // [c-within-chunk][px], stride 72 (bank-clean)
    __shared__ float Bs[32][264];     // [c-within-chunk][o],  stride 264 (bank-clean)
    __shared__ int   sbase[4][64];
    __shared__ float swt[4][64];

    int b = blockIdx.y, tile = blockIdx.x, tid = threadIdx.x;
    int lane = tid & 31, warp = tid >> 5;
    int warpM = warp & 1, warpN = warp >> 1;

    const float* xn = g_scratch + xn_o;

    float acc[2][8][4];
    #pragma unroll
    for (int mt = 0; mt < 2; ++mt)
        #pragma unroll
        for (int nt = 0; nt < 8; ++nt)
            #pragma unroll
            for (int r = 0; r < 4; ++r) acc[mt][nt][r] = 0.f;

    int gpx = tid & 63;   // gather: pixel
    int gcq = tid >> 6;   // gather: c-quad base (0..3); second item adds 4

    for (int k = 0; k < 9; ++k) {
        if (tid < 64) {
            int p = tile * 64 + tid;
            int h = p / Wo, w = p - h * Wo;
            size_t ob = off_o + ((size_t)(b * offH + h * offmul) * offW + w * offmul) * 27;
            float oy = g_scratch[ob + 2 * k];
            float ox = g_scratch[ob + 2 * k + 1];
            float m  = g_scratch[ob + 18 + k];
            float py  = (float)(h * stride - 1 + k / 3) + oy;
            float pxx = (float)(w * stride - 1 + k % 3) + ox;
            float fy = floorf(py), fx = floorf(pxx);
            int y0 = (int)fy, x0 = (int)fx;
            float wy = py - fy, wx = pxx - fx;
            int y1 = y0 + 1, x1 = x0 + 1;
            float vy0 = (y0 >= 0 && y0 < Hi) ? 1.f : 0.f;
            float vy1 = (y1 >= 0 && y1 < Hi) ? 1.f : 0.f;
            float vx0 = (x0 >= 0 && x0 < Wi) ? 1.f : 0.f;
            float vx1 = (x1 >= 0 && x1 < Wi) ? 1.f : 0.f;
            int y0c = min(max(y0, 0), Hi - 1), y1c = min(max(y1, 0), Hi - 1);
            int x0c = min(max(x0, 0), Wi - 1), x1c = min(max(x1, 0), Wi - 1);
            swt[0][tid] = (1.f - wy) * (1.f - wx) * m * vy0 * vx0;
            swt[1][tid] = (1.f - wy) * wx * m * vy0 * vx1;
            swt[2][tid] = wy * (1.f - wx) * m * vy1 * vx0;
            swt[3][tid] = wy * wx * m * vy1 * vx1;
            sbase[0][tid] = ((b * Hi + y0c) * Wi + x0c) * 256;
            sbase[1][tid] = ((b * Hi + y0c) * Wi + x1c) * 256;
            sbase[2][tid] = ((b * Hi + y1c) * Wi + x0c) * 256;
            sbase[3][tid] = ((b * Hi + y1c) * Wi + x1c) * 256;
        }
        __syncthreads();

        float w00 = swt[0][gpx], w01 = swt[1][gpx], w10 = swt[2][gpx], w11 = swt[3][gpx];
        int b00 = sbase[0][gpx], b01 = sbase[1][gpx], b10 = sbase[2][gpx], b11 = sbase[3][gpx];

        for (int c0 = 0; c0 < 256; c0 += 32) {
            // ---- gather A tile: 64 px x 32 c, weighted bilinear, tf32-rounded
            #pragma unroll
            for (int it = 0; it < 2; ++it) {
                int cq = gcq + it * 4;
                int cofs = c0 + cq * 4;
                float4 v00 = *(const float4*)(xn + b00 + cofs);
                float4 v01 = *(const float4*)(xn + b01 + cofs);
                float4 v10 = *(const float4*)(xn + b10 + cofs);
                float4 v11 = *(const float4*)(xn + b11 + cofs);
                As[cq * 4 + 0][gpx] = f2tf32(w00 * v00.x + w01 * v01.x + w10 * v10.x + w11 * v11.x);
                As[cq * 4 + 1][gpx] = f2tf32(w00 * v00.y + w01 * v01.y + w10 * v10.y + w11 * v11.y);
                As[cq * 4 + 2][gpx] = f2tf32(w00 * v00.z + w01 * v01.z + w10 * v10.z + w11 * v11.z);
                As[cq * 4 + 3][gpx] = f2tf32(w00 * v00.w + w01 * v01.w + w10 * v10.w + w11 * v11.w);
            }
            // ---- load B tile: 32 c x 256 o (already tf32-rounded)
            #pragma unroll
            for (int it = 0; it < 8; ++it) {
                int e = it * 256 + tid;
                int cc = e >> 6;
                int o4 = (e & 63) << 2;
                *(float4*)&Bs[cc][o4] =
                    *(const float4*)&g_scratch[w3_o + (((size_t)k * 256 + c0 + cc) << 8) + o4];
            }
            __syncthreads();
            // ---- 4 k8 MMA steps
            #pragma unroll
            for (int ks = 0; ks < 4; ++ks) {
                int kc = ks * 8;
                uint32_t a[2][4];
                int arow = warpM * 32 + (lane >> 2);
                int acol = kc + (lane & 3);
                #pragma unroll
                for (int mt = 0; mt < 2; ++mt) {
                    a[mt][0] = __float_as_uint(As[acol][arow + mt * 16]);
                    a[mt][1] = __float_as_uint(As[acol][arow + mt * 16 + 8]);
                    a[mt][2] = __float_as_uint(As[acol + 4][arow + mt * 16]);
                    a[mt][3] = __float_as_uint(As[acol + 4][arow + mt * 16 + 8]);
                }
                int brow = kc + (lane & 3);
                int bcol = warpN * 64 + (lane >> 2);
                #pragma unroll
                for (int nt = 0; nt < 8; ++nt) {
                    uint32_t bb0 = __float_as_uint(Bs[brow][bcol + nt * 8]);
                    uint32_t bb1 = __float_as_uint(Bs[brow + 4][bcol + nt * 8]);
                    mma_tf32(acc[0][nt], a[0], bb0, bb1);
                    mma_tf32(acc[1][nt], a[1], bb0, bb1);
                }
            }
            __syncthreads();
        }
    }

    // ---- epilogue: NCHW output [b][o][HWo]
    float* yp = g_scratch + y_o + (size_t)b * 256 * HWo;
    int px0 = tile * 64 + warpM * 32 + (lane >> 2);
    #pragma unroll
    for (int nt = 0; nt < 8; ++nt) {
        int o = warpN * 64 + nt * 8 + 2 * (lane & 3);
        #pragma unroll
        for (int mt = 0; mt < 2; ++mt) {
            int px = px0 + mt * 16;
            yp[(size_t)o * HWo + px]           = acc[mt][nt][0];
            yp[(size_t)(o + 1) * HWo + px]     = acc[mt][nt][1];
            yp[(size_t)o * HWo + px + 8]       = acc[mt][nt][2];
            yp[(size_t)(o + 1) * HWo + px + 8] = acc[mt][nt][3];
        }
    }
}

// ---------------------------------------------------------------------------
// Per-(b,c) spatial sum + sumsq over HW (NCHW input in scratch).
// ---------------------------------------------------------------------------
__global__ void chan_stats_kernel(size_t y_o, int HW, size_t sum_o, size_t sq_o) {
    int c = blockIdx.x, b = blockIdx.y, tid = threadIdx.x;
    const float4* p = (const float4*)(g_scratch + y_o + ((size_t)(b * 256 + c)) * HW);
    float s = 0.f, q = 0.f;
    for (int i = tid; i < (HW >> 2); i += 256) {
        float4 v = p[i];
        s += v.x + v.y + v.z + v.w;
        q += v.x * v.x + v.y * v.y + v.z * v.z + v.w * v.w;
    }
    #pragma unroll
    for (int o = 16; o; o >>= 1) {
        s += __shfl_down_sync(0xffffffffu, s, o);
        q += __shfl_down_sync(0xffffffffu, q, o);
    }
    __shared__ float rs[8], rq[8];
    if ((tid & 31) == 0) { rs[tid >> 5] = s; rq[tid >> 5] = q; }
    __syncthreads();
    if (tid == 0) {
        float ts = 0.f, tq = 0.f;
        #pragma unroll
        for (int i = 0; i < 8; ++i) { ts += rs[i]; tq += rq[i]; }
        g_scratch[sum_o + b * 256 + c] = ts;
        g_scratch[sq_o + b * 256 + c] = tq;
    }
}

// ---------------------------------------------------------------------------
// GN finalize: per-(b,g) mean/rstd, plus scale-attn scalar s[b] (analytic pool).
// ---------------------------------------------------------------------------
__global__ void gn_finalize_kernel(
    size_t sum_o, size_t sq_o,
    const float* __restrict__ gamma, const float* __restrict__ beta,
    const float* __restrict__ w_sa, const float* __restrict__ b_sa,
    float inv_hw, float inv_cnt,
    size_t gnm_o, size_t gnr_o, size_t sv_o)
{
    int b = blockIdx.x, t = threadIdx.x;  // 256
    __shared__ float ss[256], qq[256], gm[16], gr[16], red[256];
    ss[t] = g_scratch[sum_o + b * 256 + t];
    qq[t] = g_scratch[sq_o + b * 256 + t];
    __syncthreads();
    if (t < 16) {
        float S = 0.f, Q = 0.f;
        #pragma unroll
        for (int j = 0; j < 16; ++j) { S += ss[t * 16 + j]; Q += qq[t * 16 + j]; }
        float mean = S * inv_cnt;
        float var = Q * inv_cnt - mean * mean;
        float r = rsqrtf(var + 1e-5f);
        gm[t] = mean; gr[t] = r;
        g_scratch[gnm_o + b * 16 + t] = mean;
        g_scratch[gnr_o + b * 16 + t] = r;
    }
    __syncthreads();
    int g = t >> 4;
    float p = gamma[t] * (ss[t] * inv_hw - gm[g]) * gr[g] + beta[t];
    red[t] = p * w_sa[t];
    __syncthreads();
    for (int off = 128; off; off >>= 1) {
        if (t < off) red[t] += red[t + off];
        __syncthreads();
    }
    if (t == 0) {
        float x = fmaxf(red[0] + b_sa[0], 0.f);
        g_scratch[sv_o + b] = fminf(x + 3.f, 6.f) * (1.f / 6.f);
    }
}

__global__ void zero_kernel(size_t o, int n) {
    int i = blockIdx.x * 256 + threadIdx.x;
    if (i < n) g_scratch[o + i] = 0.f;
}

// ---------------------------------------------------------------------------
// Combine branches: GN affine + scale-attn weight + bilinear upsample (high),
// divide by n, write sum_feat, accumulate per-(b,c) pooled sums.
// ---------------------------------------------------------------------------
__global__ void combine_kernel(
    size_t ymid_o, size_t ylow_o, size_t yhigh_o,
    int hasLow, int hasHigh, int W, int HW, int Hh, int Wh, float ry, float rx,
    size_t gnm_o, size_t gnr_o, size_t sv_o,
    const float* __restrict__ gw_mid, const float* __restrict__ gb_mid,
    const float* __restrict__ gw_low, const float* __restrict__ gb_low,
    const float* __restrict__ gw_high, const float* __restrict__ gb_high,
    float inv_n, size_t sumf_o, size_t p2_o)
{
    int b = blockIdx.z, c = blockIdx.y;
    int px = blockIdx.x * 256 + threadIdx.x;
    int g = c >> 4;
    int gi = b * 16 + g;
    size_t base = ((size_t)(b * 256 + c)) * HW;

    float v = g_scratch[sv_o + b] *
              (gw_mid[c] * (g_scratch[ymid_o + base + px] - g_scratch[gnm_o + gi]) * g_scratch[gnr_o + gi] + gb_mid[c]);
    if (hasLow)
        v += g_scratch[sv_o + 2 + b] *
             (gw_low[c] * (g_scratch[ylow_o + base + px] - g_scratch[gnm_o + 32 + gi]) * g_scratch[gnr_o + 32 + gi] + gb_low[c]);
    if (hasHigh) {
        int h = px / W, w = px - h * W;
        float sy = h * ry, sx = w * rx;
        int yl = (int)sy; int yh2 = min(yl + 1, Hh - 1);
        int xl = (int)sx; int xh = min(xl + 1, Wh - 1);
        float wy = sy - (float)yl, wx = sx - (float)xl;
        const float* hp = g_scratch + yhigh_o + ((size_t)(b * 256 + c)) * Hh * Wh;
        float t0 = hp[yl * Wh + xl] * (1.f - wx) + hp[yl * Wh + xh] * wx;
        float t1 = hp[yh2 * Wh + xl] * (1.f - wx) + hp[yh2 * Wh + xh] * wx;
        float raw = t0 * (1.f - wy) + t1 * wy;
        v += g_scratch[sv_o + 4 + b] *
             (gw_high[c] * (raw - g_scratch[gnm_o + 64 + gi]) * g_scratch[gnr_o + 64 + gi] + gb_high[c]);
    }
    v *= inv_n;
    g_scratch[sumf_o + base + px] = v;

    float r = v;
    #pragma unroll
    for (int o = 16; o; o >>= 1) r += __shfl_down_sync(0xffffffffu, r, o);
    __shared__ float wsum[8];
    if ((threadIdx.x & 31) == 0) wsum[threadIdx.x >> 5] = r;
    __syncthreads();
    if (threadIdx.x == 0) {
        float tt = 0.f;
        #pragma unroll
        for (int i = 0; i < 8; ++i) tt += wsum[i];
        atomicAdd(&g_scratch[p2_o + b * 256 + c], tt);
    }
}

// ---------------------------------------------------------------------------
// DyReLU coefficients.
// ---------------------------------------------------------------------------
__global__ void dycoef_kernel(size_t p2_o, float inv_hw,
    const float* __restrict__ w1, const float* __restrict__ b1,
    const float* __restrict__ w2, const float* __restrict__ b2,
    size_t coef_o)
{
    int b = blockIdx.x, t = threadIdx.x;  // 1024
    __shared__ float pm[256], hb[64];
    if (t < 256) pm[t] = g_scratch[p2_o + b * 256 + t] * inv_hw;
    __syncthreads();
    if (t < 64) {
        float a = b1[t];
        for (int cx = 0; cx < 256; ++cx) a += pm[cx] * w1[t * 256 + cx];
        hb[t] = fmaxf(a, 0.f);
    }
    __syncthreads();
    float a = b2[t];
    #pragma unroll
    for (int i = 0; i < 64; ++i) a += hb[i] * w2[t * 64 + i];
    float hs = fminf(fmaxf(a + 3.f, 0.f), 6.f) * (1.f / 6.f);
    g_scratch[coef_o + b * 1024 + t] = hs - 0.5f;
}

// ---------------------------------------------------------------------------
// Apply DyReLU, write final output.
// ---------------------------------------------------------------------------
__global__ void dyrelu_kernel(size_t sumf_o, size_t coef_o, int HW, float* __restrict__ outp, int CHW) {
    int idx = blockIdx.x * 256 + threadIdx.x;
    int b = idx / CHW;
    int c = (idx - b * CHW) / HW;
    const float* cf = g_scratch + coef_o + b * 1024;
    float x = g_scratch[sumf_o + idx];
    float a1 = cf[c] * 2.f + 1.f, bb1 = cf[256 + c];
    float a2 = cf[512 + c] * 2.f, bb2 = cf[768 + c];
    outp[idx] = fmaxf(x * a1 + bb1, x * a2 + bb2);
}

// ---------------------------------------------------------------------------
// Host orchestration
// ---------------------------------------------------------------------------
extern "C" void kernel_launch(void* const* d_in, const int* in_sizes, int n_in,
                              void* d_out, int out_size) {
    (void)in_sizes; (void)n_in; (void)out_size;
    const float* x0     = (const float*)d_in[0];
    const float* x1     = (const float*)d_in[1];
    const float* x2     = (const float*)d_in[2];
    const float* w_off  = (const float*)d_in[3];
    const float* b_off  = (const float*)d_in[4];
    const float* w_mid  = (const float*)d_in[5];
    const float* g_mid  = (const float*)d_in[6];
    const float* be_mid = (const float*)d_in[7];
    const float* w_low  = (const float*)d_in[8];
    const float* g_low  = (const float*)d_in[9];
    const float* be_low = (const float*)d_in[10];
    const float* w_high = (const float*)d_in[11];
    const float* g_high = (const float*)d_in[12];
    const float* be_high= (const float*)d_in[13];
    const float* w_sa   = (const float*)d_in[14];
    const float* b_sa   = (const float*)d_in[15];
    const float* w_dy1  = (const float*)d_in[16];
    const float* b_dy1  = (const float*)d_in[17];
    const float* w_dy2  = (const float*)d_in[18];
    const float* b_dy2  = (const float*)d_in[19];
    float* out = (float*)d_out;

    // weight reorders (mid/low/high tf32-rounded for MMA)
    reorder_w_tf32_kernel<<<2304, 256>>>(w_mid,  OFF_W3MID);
    reorder_w_tf32_kernel<<<2304, 256>>>(w_low,  OFF_W3LOW);
    reorder_w_tf32_kernel<<<2304, 256>>>(w_high, OFF_W3HIGH);
    reorder_woff_kernel<<<288, 256>>>(w_off, OFF_W3OFF);

    // NCHW -> NHWC transposes
    {
        dim3 blk(32, 8);
        transpose_kernel<<<dim3(128 * 128 / 32, 8, 2), blk>>>(x0, OFF_X0N, 128 * 128);
        transpose_kernel<<<dim3(64 * 64 / 32, 8, 2), blk>>>(x1, OFF_X1N, 64 * 64);
        transpose_kernel<<<dim3(32 * 32 / 32, 8, 2), blk>>>(x2, OFF_X2N, 32 * 32);
    }

    const int Hs[3] = {128, 64, 32};
    const size_t xn_offs[3] = {OFF_X0N, OFF_X1N, OFF_X2N};
    size_t outoff = 0;

    for (int l = 0; l < 3; ++l) {
        int H = Hs[l], HW = H * H;
        int hasLow = (l > 0), hasHigh = (l < 2);
        int nbr = 1 + hasLow + hasHigh;

        // offset conv
        offconv_kernel<<<dim3(HW / 128, 2), 256>>>(xn_offs[l], H, H, OFF_W3OFF, b_off, OFF_OFFB);

        // mid branch
        mdconv_mma_kernel<<<dim3(HW / 64, 2), 256>>>(xn_offs[l], H, H, OFF_OFFB, H, H, 1, 1,
                                                     OFF_W3MID, OFF_YMID, HW, H);
        chan_stats_kernel<<<dim3(256, 2), 256>>>(OFF_YMID, HW, OFF_CHSUM, OFF_CHSQ);
        gn_finalize_kernel<<<2, 256>>>(OFF_CHSUM, OFF_CHSQ, g_mid, be_mid, w_sa, b_sa,
                                       1.f / HW, 1.f / (16.f * HW),
                                       OFF_GNM, OFF_GNR, OFF_SV);
        // low branch
        if (hasLow) {
            int Hi = Hs[l - 1];
            mdconv_mma_kernel<<<dim3(HW / 64, 2), 256>>>(xn_offs[l - 1], Hi, Hi, OFF_OFFB, H, H, 1, 2,
                                                         OFF_W3LOW, OFF_YLOW, HW, H);
            chan_stats_kernel<<<dim3(256, 2), 256>>>(OFF_YLOW, HW, OFF_CHSUM, OFF_CHSQ);
            gn_finalize_kernel<<<2, 256>>>(OFF_CHSUM, OFF_CHSQ, g_low, be_low, w_sa, b_sa,
                                           1.f / HW, 1.f / (16.f * HW),
                                           OFF_GNM + 32, OFF_GNR + 32, OFF_SV + 2);
        }
        // high branch
        int Hh = H / 2, HWh = Hh * Hh;
        if (hasHigh) {
            mdconv_mma_kernel<<<dim3(HWh / 64, 2), 256>>>(xn_offs[l + 1], Hh, Hh, OFF_OFFB, H, H, 2, 1,
                                                          OFF_W3HIGH, OFF_YHIGH, HWh, Hh);
            chan_stats_kernel<<<dim3(256, 2), 256>>>(OFF_YHIGH, HWh, OFF_CHSUM, OFF_CHSQ);
            gn_finalize_kernel<<<2, 256>>>(OFF_CHSUM, OFF_CHSQ, g_high, be_high, w_sa, b_sa,
                                           1.f / HWh, 1.f / (16.f * HWh),
                                           OFF_GNM + 64, OFF_GNR + 64, OFF_SV + 4);
        }

        zero_kernel<<<2, 256>>>(OFF_P2, 512);
        float ry = (float)(Hh - 1) / (float)(H - 1);
        combine_kernel<<<dim3(HW / 256, 256, 2), 256>>>(
            OFF_YMID, OFF_YLOW, OFF_YHIGH, hasLow, hasHigh,
            H, HW, Hh, Hh, ry, ry,
            OFF_GNM, OFF_GNR, OFF_SV,
            g_mid, be_mid, g_low, be_low, g_high, be_high,
            1.f / (float)nbr, OFF_SUMF, OFF_P2);

        dycoef_kernel<<<2, 1024>>>(OFF_P2, 1.f / HW, w_dy1, b_dy1, w_dy2, b_dy2, OFF_COEF);

        int total = 2 * 256 * HW;
        dyrelu_kernel<<<total / 256, 256>>>(OFF_SUMF, OFF_COEF, HW, out + outoff, 256 * HW);
        outoff += (size_t)total;
    }
}

// round 4
// speedup vs baseline: 1.6212x; 1.1601x over previous
#include <cuda_runtime.h>
#include <math.h>
#include <stdint.h>

// ---------------------------------------------------------------------------
// DyHead-style MultiAttentionBlock. fp32 + TF32 tensor-core mdconv (pipelined).
// B=2, C=256, levels H = {128, 64, 32}, GN groups = 16.
// ---------------------------------------------------------------------------

constexpr int BN = 2;
constexpr int C  = 256;

// ---- scratch layout (floats) ----
constexpr size_t OFF_X0N   = 0;
constexpr size_t OFF_X1N   = OFF_X0N  + (size_t)BN*128*128*C;
constexpr size_t OFF_X2N   = OFF_X1N  + (size_t)BN*64*64*C;
constexpr size_t OFF_OFFB  = OFF_X2N  + (size_t)BN*32*32*C;
constexpr size_t OFF_YMID  = OFF_OFFB + (size_t)BN*128*128*27;
constexpr size_t OFF_YLOW  = OFF_YMID + (size_t)BN*C*128*128;
constexpr size_t OFF_YHIGH = OFF_YLOW + (size_t)BN*C*64*64;
constexpr size_t OFF_SUMF  = OFF_YHIGH+ (size_t)BN*C*64*64;
constexpr size_t OFF_W3MID = OFF_SUMF + (size_t)BN*C*128*128;
constexpr size_t OFF_W3LOW = OFF_W3MID + (size_t)9*256*256;
constexpr size_t OFF_W3HIGH= OFF_W3LOW + (size_t)9*256*256;
constexpr size_t OFF_W3OFF = OFF_W3HIGH+ (size_t)9*256*256;
constexpr size_t OFF_CHSUM = OFF_W3OFF + (size_t)9*256*32;
constexpr size_t OFF_CHSQ  = OFF_CHSUM + 512;
constexpr size_t OFF_GNM   = OFF_CHSQ  + 512;
constexpr size_t OFF_GNR   = OFF_GNM   + 96;
constexpr size_t OFF_SV    = OFF_GNR   + 96;
constexpr size_t OFF_P2    = OFF_SV    + 8;
constexpr size_t OFF_COEF  = OFF_P2    + 512;
constexpr size_t SCRATCH_TOTAL = OFF_COEF + 2048;

__device__ __align__(256) float g_scratch[SCRATCH_TOTAL];

// dynamic smem layout for mdconv (floats):
//   As   : [2][32][72]   at 0        (4608 floats)
//   Bs   : [2][32][264]  at 4608     (16896 floats)
//   swt9 : [9][4][64]    at 21504    (2304 floats)
//   sb9  : [9][4][64]    at 23808    (2304 ints)
constexpr int MD_AS   = 0;
constexpr int MD_BS   = 4608;
constexpr int MD_SWT  = 21504;
constexpr int MD_SB   = 23808;
constexpr int MD_SMEM_BYTES = (23808 + 2304) * 4;   // 104448

__device__ __forceinline__ float f2tf32(float f) {
    uint32_t r;
    asm("cvt.rna.tf32.f32 %0, %1;" : "=r"(r) : "f"(f));
    return __uint_as_float(r);
}

__device__ __forceinline__ void mma_tf32(float* d, const uint32_t* a, uint32_t b0, uint32_t b1) {
    asm volatile(
        "mma.sync.aligned.m16n8k8.row.col.f32.tf32.tf32.f32 "
        "{%0,%1,%2,%3},{%4,%5,%6,%7},{%8,%9},{%0,%1,%2,%3};\n"
        : "+f"(d[0]), "+f"(d[1]), "+f"(d[2]), "+f"(d[3])
        : "r"(a[0]), "r"(a[1]), "r"(a[2]), "r"(a[3]), "r"(b0), "r"(b1));
}

__device__ __forceinline__ void cp_async16(uint32_t daddr, const void* src) {
    asm volatile("cp.async.cg.shared.global [%0], [%1], 16;\n" :: "r"(daddr), "l"(src));
}

// ---------------------------------------------------------------------------
// Weight reorders: OIHW (O,C,3,3) -> [k][c][o], tf32-rounded for MMA weights.
// ---------------------------------------------------------------------------
__global__ void reorder_w_tf32_kernel(const float* __restrict__ w, size_t out_o) {
    int idx = blockIdx.x * 256 + threadIdx.x;       // < 9*256*256
    int o = idx & 255, c = (idx >> 8) & 255, k = idx >> 16;
    g_scratch[out_o + idx] = f2tf32(w[(o * 256 + c) * 9 + k]);
}

__global__ void reorder_woff_kernel(const float* __restrict__ w, size_t out_o) {
    int idx = blockIdx.x * 256 + threadIdx.x;       // < 9*256*32
    int o = idx & 31, c = (idx >> 5) & 255, k = idx >> 13;
    g_scratch[out_o + idx] = (o < 27) ? w[(o * 256 + c) * 9 + k] : 0.f;
}

// ---------------------------------------------------------------------------
// NCHW -> NHWC transpose.
// ---------------------------------------------------------------------------
__global__ void transpose_kernel(const float* __restrict__ in, size_t out_o, int HW) {
    __shared__ float t[32][33];
    int b = blockIdx.z;
    int hw0 = blockIdx.x * 32, c0 = blockIdx.y * 32;
    int tx = threadIdx.x, ty = threadIdx.y;  // 32 x 8
    #pragma unroll
    for (int i = 0; i < 32; i += 8)
        t[ty + i][tx] = in[((size_t)b * C + c0 + ty + i) * HW + hw0 + tx];
    __syncthreads();
    #pragma unroll
    for (int i = 0; i < 32; i += 8)
        g_scratch[out_o + ((size_t)b * HW + hw0 + ty + i) * C + c0 + tx] = t[tx][ty + i];
}

// ---------------------------------------------------------------------------
// Offset conv: 3x3, 256 -> 27 (padded to 32), zero-pad. fp32 SIMT.
// ---------------------------------------------------------------------------
__global__ __launch_bounds__(256) void offconv_kernel(
    size_t xn_o, int H, int W,
    size_t w3_o, const float* __restrict__ bias, size_t out_o)
{
    int b = blockIdx.y, tile = blockIdx.x, tid = threadIdx.x;
    __shared__ float As[16][128];
    __shared__ float Bs[16][32];
    int o = tid & 31, pxg = tid >> 5;
    const float* xn = g_scratch + xn_o;

    float acc[16];
    #pragma unroll
    for (int j = 0; j < 16; ++j) acc[j] = 0.f;

    for (int k = 0; k < 9; ++k) {
        int dy = k / 3 - 1, dx = k % 3 - 1;
        for (int c0 = 0; c0 < 256; c0 += 16) {
            __syncthreads();
            #pragma unroll
            for (int i = 0; i < 2; ++i) {
                int e4 = i * 256 + tid;
                int px = e4 >> 2, cq = e4 & 3;
                int p = tile * 128 + px;
                int h = p / W, w = p - h * W;
                int y = h + dy, x = w + dx;
                float4 v = make_float4(0.f, 0.f, 0.f, 0.f);
                if (y >= 0 && y < H && x >= 0 && x < W)
                    v = *(const float4*)(xn + ((size_t)(b * H + y) * W + x) * 256 + c0 + cq * 4);
                As[cq * 4 + 0][px] = v.x;
                As[cq * 4 + 1][px] = v.y;
                As[cq * 4 + 2][px] = v.z;
                As[cq * 4 + 3][px] = v.w;
            }
            #pragma unroll
            for (int i = 0; i < 2; ++i) {
                int e = i * 256 + tid;
                int cc = e >> 5, oo = e & 31;
                Bs[cc][oo] = g_scratch[w3_o + ((size_t)(k * 256 + c0 + cc) << 5) + oo];
            }
            __syncthreads();
            #pragma unroll
            for (int cc = 0; cc < 16; ++cc) {
                float bb = Bs[cc][o];
                float4 a0 = *(const float4*)&As[cc][pxg * 16 + 0];
                float4 a1 = *(const float4*)&As[cc][pxg * 16 + 4];
                float4 a2 = *(const float4*)&As[cc][pxg * 16 + 8];
                float4 a3 = *(const float4*)&As[cc][pxg * 16 + 12];
                acc[0]  += a0.x * bb; acc[1]  += a0.y * bb; acc[2]  += a0.z * bb; acc[3]  += a0.w * bb;
                acc[4]  += a1.x * bb; acc[5]  += a1.y * bb; acc[6]  += a1.z * bb; acc[7]  += a1.w * bb;
                acc[8]  += a2.x * bb; acc[9]  += a2.y * bb; acc[10] += a2.z * bb; acc[11] += a2.w * bb;
                acc[12] += a3.x * bb; acc[13] += a3.y * bb; acc[14] += a3.z * bb; acc[15] += a3.w * bb;
            }
        }
    }
    if (o < 27) {
        float bv = bias[o];
        #pragma unroll
        for (int j = 0; j < 16; ++j) {
            int p = tile * 128 + pxg * 16 + j;
            int h = p / W, w = p - h * W;
            float v = acc[j] + bv;
            if (o >= 18) v = 1.f / (1.f + expf(-v));
            g_scratch[out_o + ((size_t)(b * H + h) * W + w) * 27 + o] = v;
        }
    }
}

// ---------------------------------------------------------------------------
// Modulated deformable conv: fused bilinear gather + TF32 MMA, software
// pipelined (double-buffered As/Bs, cp.async B tiles, gather LDG prefetch).
// Block: 64 px x 256 o, 256 threads (8 warps = 2M x 4N). 72 steps of 32-c.
// ---------------------------------------------------------------------------
__global__ __launch_bounds__(256) void mdconv_mma_kernel(
    size_t xn_o, int Hi, int Wi,
    size_t off_o, int offH, int offW, int offmul,
    int stride, size_t w3_o,
    size_t y_o, int HWo, int Wo)
{
    extern __shared__ float smem[];
    float* As   = smem + MD_AS;
    float* Bs   = smem + MD_BS;
    float* swt9 = smem + MD_SWT;
    int*   sb9  = (int*)(smem + MD_SB);

    int b = blockIdx.y, tile = blockIdx.x, tid = threadIdx.x;
    int lane = tid & 31, warp = tid >> 5;
    int warpM = warp & 1, warpN = warp >> 1;

    const float* xn = g_scratch + xn_o;

    // ---- precompute all 9 k gather tables
    for (int it = tid; it < 576; it += 256) {
        int k = it >> 6, p = it & 63;
        int pg = tile * 64 + p;
        int h = pg / Wo, w = pg - h * Wo;
        size_t ob = off_o + ((size_t)(b * offH + h * offmul) * offW + w * offmul) * 27;
        float oy = g_scratch[ob + 2 * k];
        float ox = g_scratch[ob + 2 * k + 1];
        float m  = g_scratch[ob + 18 + k];
        float py  = (float)(h * stride - 1 + k / 3) + oy;
        float pxx = (float)(w * stride - 1 + k % 3) + ox;
        float fy = floorf(py), fx = floorf(pxx);
        int y0 = (int)fy, x0 = (int)fx;
        float wy = py - fy, wx = pxx - fx;
        int y1 = y0 + 1, x1 = x0 + 1;
        float vy0 = (y0 >= 0 && y0 < Hi) ? 1.f : 0.f;
        float vy1 = (y1 >= 0 && y1 < Hi) ? 1.f : 0.f;
        float vx0 = (x0 >= 0 && x0 < Wi) ? 1.f : 0.f;
        float vx1 = (x1 >= 0 && x1 < Wi) ? 1.f : 0.f;
        int y0c = min(max(y0, 0), Hi - 1), y1c = min(max(y1, 0), Hi - 1);
        int x0c = min(max(x0, 0), Wi - 1), x1c = min(max(x1, 0), Wi - 1);
        int kb = k * 256 + p;
        swt9[kb]       = (1.f - wy) * (1.f - wx) * m * vy0 * vx0;
        swt9[kb + 64]  = (1.f - wy) * wx * m * vy0 * vx1;
        swt9[kb + 128] = wy * (1.f - wx) * m * vy1 * vx0;
        swt9[kb + 192] = wy * wx * m * vy1 * vx1;
        sb9[kb]       = ((b * Hi + y0c) * Wi + x0c) * 256;
        sb9[kb + 64]  = ((b * Hi + y0c) * Wi + x1c) * 256;
        sb9[kb + 128] = ((b * Hi + y1c) * Wi + x0c) * 256;
        sb9[kb + 192] = ((b * Hi + y1c) * Wi + x1c) * 256;
    }
    __syncthreads();

    float acc[2][8][4];
    #pragma unroll
    for (int mt = 0; mt < 2; ++mt)
        #pragma unroll
        for (int nt = 0; nt < 8; ++nt)
            #pragma unroll
            for (int r = 0; r < 4; ++r) acc[mt][nt][r] = 0.f;

    int gpx = tid & 63;
    int gcq = tid >> 6;     // 0..3

    uint32_t bs_saddr = (uint32_t)__cvta_generic_to_shared(Bs);

    // gather staging regs
    float gw0, gw1, gw2, gw3;
    float4 gv0[2], gv1[2], gv2[2], gv3[2];

    auto gather_ldg = [&](int s) {
        int kk = s >> 3, c0n = (s & 7) << 5;
        int kb = kk * 256 + gpx;
        gw0 = swt9[kb]; gw1 = swt9[kb + 64]; gw2 = swt9[kb + 128]; gw3 = swt9[kb + 192];
        int b00 = sb9[kb], b01 = sb9[kb + 64], b10 = sb9[kb + 128], b11 = sb9[kb + 192];
        #pragma unroll
        for (int it = 0; it < 2; ++it) {
            int cofs = c0n + (gcq + it * 4) * 4;
            gv0[it] = *(const float4*)(xn + b00 + cofs);
            gv1[it] = *(const float4*)(xn + b01 + cofs);
            gv2[it] = *(const float4*)(xn + b10 + cofs);
            gv3[it] = *(const float4*)(xn + b11 + cofs);
        }
    };
    auto combine_sts = [&](int buf) {
        #pragma unroll
        for (int it = 0; it < 2; ++it) {
            int cq = gcq + it * 4;
            float* dst = As + buf * 2304 + cq * 4 * 72 + gpx;
            dst[0]   = f2tf32(gw0 * gv0[it].x + gw1 * gv1[it].x + gw2 * gv2[it].x + gw3 * gv3[it].x);
            dst[72]  = f2tf32(gw0 * gv0[it].y + gw1 * gv1[it].y + gw2 * gv2[it].y + gw3 * gv3[it].y);
            dst[144] = f2tf32(gw0 * gv0[it].z + gw1 * gv1[it].z + gw2 * gv2[it].z + gw3 * gv3[it].z);
            dst[216] = f2tf32(gw0 * gv0[it].w + gw1 * gv1[it].w + gw2 * gv2[it].w + gw3 * gv3[it].w);
        }
    };
    auto cpasync_b = [&](int s, int buf) {
        int kk = s >> 3, c0n = (s & 7) << 5;
        const float* wsrc = g_scratch + w3_o + (((size_t)kk * 256 + c0n) << 8);
        #pragma unroll
        for (int it = 0; it < 8; ++it) {
            int e = it * 256 + tid;
            int cc = e >> 6;
            int o4 = (e & 63) << 2;
            cp_async16(bs_saddr + (uint32_t)(buf * 8448 + cc * 264 + o4) * 4u,
                       wsrc + cc * 256 + o4);
        }
        asm volatile("cp.async.commit_group;\n");
    };

    // prologue: step 0
    gather_ldg(0);
    cpasync_b(0, 0);

    for (int s = 0; s < 72; ++s) {
        int cb = s & 1, nb = cb ^ 1;
        combine_sts(cb);
        if (s < 71) gather_ldg(s + 1);
        asm volatile("cp.async.wait_group 0;\n");
        __syncthreads();
        if (s < 71) cpasync_b(s + 1, nb);

        const float* Ab = As + cb * 2304;
        const float* Bb = Bs + cb * 8448;
        #pragma unroll
        for (int ks = 0; ks < 4; ++ks) {
            int kc = ks * 8;
            int arow = warpM * 32 + (lane >> 2);
            int acol = kc + (lane & 3);
            uint32_t a[2][4];
            #pragma unroll
            for (int mt = 0; mt < 2; ++mt) {
                a[mt][0] = __float_as_uint(Ab[acol * 72 + arow + mt * 16]);
                a[mt][1] = __float_as_uint(Ab[acol * 72 + arow + mt * 16 + 8]);
                a[mt][2] = __float_as_uint(Ab[(acol + 4) * 72 + arow + mt * 16]);
                a[mt][3] = __float_as_uint(Ab[(acol + 4) * 72 + arow + mt * 16 + 8]);
            }
            int brow = kc + (lane & 3);
            int bcol = warpN * 64 + (lane >> 2);
            #pragma unroll
            for (int nt = 0; nt < 8; ++nt) {
                uint32_t bb0 = __float_as_uint(Bb[brow * 264 + bcol + nt * 8]);
                uint32_t bb1 = __float_as_uint(Bb[(brow + 4) * 264 + bcol + nt * 8]);
                mma_tf32(acc[0][nt], a[0], bb0, bb1);
                mma_tf32(acc[1][nt], a[1], bb0, bb1);
            }
        }
    }

    // ---- epilogue: NCHW output [b][o][HWo]
    float* yp = g_scratch + y_o + (size_t)b * 256 * HWo;
    int px0 = tile * 64 + warpM * 32 + (lane >> 2);
    #pragma unroll
    for (int nt = 0; nt < 8; ++nt) {
        int o = warpN * 64 + nt * 8 + 2 * (lane & 3);
        #pragma unroll
        for (int mt = 0; mt < 2; ++mt) {
            int px = px0 + mt * 16;
            yp[(size_t)o * HWo + px]           = acc[mt][nt][0];
            yp[(size_t)(o + 1) * HWo + px]     = acc[mt][nt][1];
            yp[(size_t)o * HWo + px + 8]       = acc[mt][nt][2];
            yp[(size_t)(o + 1) * HWo + px + 8] = acc[mt][nt][3];
        }
    }
}

// ---------------------------------------------------------------------------
// Per-(b,c) spatial sum + sumsq over HW.
// ---------------------------------------------------------------------------
__global__ void chan_stats_kernel(size_t y_o, int HW, size_t sum_o, size_t sq_o) {
    int c = blockIdx.x, b = blockIdx.y, tid = threadIdx.x;
    const float4* p = (const float4*)(g_scratch + y_o + ((size_t)(b * 256 + c)) * HW);
    float s = 0.f, q = 0.f;
    for (int i = tid; i < (HW >> 2); i += 256) {
        float4 v = p[i];
        s += v.x + v.y + v.z + v.w;
        q += v.x * v.x + v.y * v.y + v.z * v.z + v.w * v.w;
    }
    #pragma unroll
    for (int o = 16; o; o >>= 1) {
        s += __shfl_down_sync(0xffffffffu, s, o);
        q += __shfl_down_sync(0xffffffffu, q, o);
    }
    __shared__ float rs[8], rq[8];
    if ((tid & 31) == 0) { rs[tid >> 5] = s; rq[tid >> 5] = q; }
    __syncthreads();
    if (tid == 0) {
        float ts = 0.f, tq = 0.f;
        #pragma unroll
        for (int i = 0; i < 8; ++i) { ts += rs[i]; tq += rq[i]; }
        g_scratch[sum_o + b * 256 + c] = ts;
        g_scratch[sq_o + b * 256 + c] = tq;
    }
}

// ---------------------------------------------------------------------------
// GN finalize + scale-attn scalar (analytic pooled value).
// ---------------------------------------------------------------------------
__global__ void gn_finalize_kernel(
    size_t sum_o, size_t sq_o,
    const float* __restrict__ gamma, const float* __restrict__ beta,
    const float* __restrict__ w_sa, const float* __restrict__ b_sa,
    float inv_hw, float inv_cnt,
    size_t gnm_o, size_t gnr_o, size_t sv_o)
{
    int b = blockIdx.x, t = threadIdx.x;  // 256
    __shared__ float ss[256], qq[256], gm[16], gr[16], red[256];
    ss[t] = g_scratch[sum_o + b * 256 + t];
    qq[t] = g_scratch[sq_o + b * 256 + t];
    __syncthreads();
    if (t < 16) {
        float S = 0.f, Q = 0.f;
        #pragma unroll
        for (int j = 0; j < 16; ++j) { S += ss[t * 16 + j]; Q += qq[t * 16 + j]; }
        float mean = S * inv_cnt;
        float var = Q * inv_cnt - mean * mean;
        float r = rsqrtf(var + 1e-5f);
        gm[t] = mean; gr[t] = r;
        g_scratch[gnm_o + b * 16 + t] = mean;
        g_scratch[gnr_o + b * 16 + t] = r;
    }
    __syncthreads();
    int g = t >> 4;
    float p = gamma[t] * (ss[t] * inv_hw - gm[g]) * gr[g] + beta[t];
    red[t] = p * w_sa[t];
    __syncthreads();
    for (int off = 128; off; off >>= 1) {
        if (t < off) red[t] += red[t + off];
        __syncthreads();
    }
    if (t == 0) {
        float x = fmaxf(red[0] + b_sa[0], 0.f);
        g_scratch[sv_o + b] = fminf(x + 3.f, 6.f) * (1.f / 6.f);
    }
}

__global__ void zero_kernel(size_t o, int n) {
    int i = blockIdx.x * 256 + threadIdx.x;
    if (i < n) g_scratch[o + i] = 0.f;
}

// ---------------------------------------------------------------------------
// Combine branches + pooled sums.
// ---------------------------------------------------------------------------
__global__ void combine_kernel(
    size_t ymid_o, size_t ylow_o, size_t yhigh_o,
    int hasLow, int hasHigh, int W, int HW, int Hh, int Wh, float ry, float rx,
    size_t gnm_o, size_t gnr_o, size_t sv_o,
    const float* __restrict__ gw_mid, const float* __restrict__ gb_mid,
    const float* __restrict__ gw_low, const float* __restrict__ gb_low,
    const float* __restrict__ gw_high, const float* __restrict__ gb_high,
    float inv_n, size_t sumf_o, size_t p2_o)
{
    int b = blockIdx.z, c = blockIdx.y;
    int px = blockIdx.x * 256 + threadIdx.x;
    int g = c >> 4;
    int gi = b * 16 + g;
    size_t base = ((size_t)(b * 256 + c)) * HW;

    float v = g_scratch[sv_o + b] *
              (gw_mid[c] * (g_scratch[ymid_o + base + px] - g_scratch[gnm_o + gi]) * g_scratch[gnr_o + gi] + gb_mid[c]);
    if (hasLow)
        v += g_scratch[sv_o + 2 + b] *
             (gw_low[c] * (g_scratch[ylow_o + base + px] - g_scratch[gnm_o + 32 + gi]) * g_scratch[gnr_o + 32 + gi] + gb_low[c]);
    if (hasHigh) {
        int h = px / W, w = px - h * W;
        float sy = h * ry, sx = w * rx;
        int yl = (int)sy; int yh2 = min(yl + 1, Hh - 1);
        int xl = (int)sx; int xh = min(xl + 1, Wh - 1);
        float wy = sy - (float)yl, wx = sx - (float)xl;
        const float* hp = g_scratch + yhigh_o + ((size_t)(b * 256 + c)) * Hh * Wh;
        float t0 = hp[yl * Wh + xl] * (1.f - wx) + hp[yl * Wh + xh] * wx;
        float t1 = hp[yh2 * Wh + xl] * (1.f - wx) + hp[yh2 * Wh + xh] * wx;
        float raw = t0 * (1.f - wy) + t1 * wy;
        v += g_scratch[sv_o + 4 + b] *
             (gw_high[c] * (raw - g_scratch[gnm_o + 64 + gi]) * g_scratch[gnr_o + 64 + gi] + gb_high[c]);
    }
    v *= inv_n;
    g_scratch[sumf_o + base + px] = v;

    float r = v;
    #pragma unroll
    for (int o = 16; o; o >>= 1) r += __shfl_down_sync(0xffffffffu, r, o);
    __shared__ float wsum[8];
    if ((threadIdx.x & 31) == 0) wsum[threadIdx.x >> 5] = r;
    __syncthreads();
    if (threadIdx.x == 0) {
        float tt = 0.f;
        #pragma unroll
        for (int i = 0; i < 8; ++i) tt += wsum[i];
        atomicAdd(&g_scratch[p2_o + b * 256 + c], tt);
    }
}

// ---------------------------------------------------------------------------
// DyReLU coefficients.
// ---------------------------------------------------------------------------
__global__ void dycoef_kernel(size_t p2_o, float inv_hw,
    const float* __restrict__ w1, const float* __restrict__ b1,
    const float* __restrict__ w2, const float* __restrict__ b2,
    size_t coef_o)
{
    int b = blockIdx.x, t = threadIdx.x;  // 1024
    __shared__ float pm[256], hb[64];
    if (t < 256) pm[t] = g_scratch[p2_o + b * 256 + t] * inv_hw;
    __syncthreads();
    if (t < 64) {
        float a = b1[t];
        for (int cx = 0; cx < 256; ++cx) a += pm[cx] * w1[t * 256 + cx];
        hb[t] = fmaxf(a, 0.f);
    }
    __syncthreads();
    float a = b2[t];
    #pragma unroll
    for (int i = 0; i < 64; ++i) a += hb[i] * w2[t * 64 + i];
    float hs = fminf(fmaxf(a + 3.f, 0.f), 6.f) * (1.f / 6.f);
    g_scratch[coef_o + b * 1024 + t] = hs - 0.5f;
}

// ---------------------------------------------------------------------------
// Apply DyReLU, write final output.
// ---------------------------------------------------------------------------
__global__ void dyrelu_kernel(size_t sumf_o, size_t coef_o, int HW, float* __restrict__ outp, int CHW) {
    int idx = blockIdx.x * 256 + threadIdx.x;
    int b = idx / CHW;
    int c = (idx - b * CHW) / HW;
    const float* cf = g_scratch + coef_o + b * 1024;
    float x = g_scratch[sumf_o + idx];
    float a1 = cf[c] * 2.f + 1.f, bb1 = cf[256 + c];
    float a2 = cf[512 + c] * 2.f, bb2 = cf[768 + c];
    outp[idx] = fmaxf(x * a1 + bb1, x * a2 + bb2);
}

// ---------------------------------------------------------------------------
// Host orchestration
// ---------------------------------------------------------------------------
extern "C" void kernel_launch(void* const* d_in, const int* in_sizes, int n_in,
                              void* d_out, int out_size) {
    (void)in_sizes; (void)n_in; (void)out_size;
    const float* x0     = (const float*)d_in[0];
    const float* x1     = (const float*)d_in[1];
    const float* x2     = (const float*)d_in[2];
    const float* w_off  = (const float*)d_in[3];
    const float* b_off  = (const float*)d_in[4];
    const float* w_mid  = (const float*)d_in[5];
    const float* g_mid  = (const float*)d_in[6];
    const float* be_mid = (const float*)d_in[7];
    const float* w_low  = (const float*)d_in[8];
    const float* g_low  = (const float*)d_in[9];
    const float* be_low = (const float*)d_in[10];
    const float* w_high = (const float*)d_in[11];
    const float* g_high = (const float*)d_in[12];
    const float* be_high= (const float*)d_in[13];
    const float* w_sa   = (const float*)d_in[14];
    const float* b_sa   = (const float*)d_in[15];
    const float* w_dy1  = (const float*)d_in[16];
    const float* b_dy1  = (const float*)d_in[17];
    const float* w_dy2  = (const float*)d_in[18];
    const float* b_dy2  = (const float*)d_in[19];
    float* out = (float*)d_out;

    static bool attr_set = false;
    if (!attr_set) {
        cudaFuncSetAttribute(mdconv_mma_kernel,
                             cudaFuncAttributeMaxDynamicSharedMemorySize, MD_SMEM_BYTES);
        attr_set = true;
    }

    dim3 tblk(32, 8);

    // Launch order chosen so ncu's fixed window (-s 5 -c 1) lands on a heavy
    // kernel: slot 4 = offconv L0, slot 6 = mdconv mid L0.
    reorder_w_tf32_kernel<<<2304, 256>>>(w_mid,  OFF_W3MID);                    // 1
    transpose_kernel<<<dim3(128 * 128 / 32, 8, 2), tblk>>>(x0, OFF_X0N, 128 * 128); // 2
    reorder_woff_kernel<<<288, 256>>>(w_off, OFF_W3OFF);                        // 3
    offconv_kernel<<<dim3(128 * 128 / 128, 2), 256>>>(OFF_X0N, 128, 128, OFF_W3OFF, b_off, OFF_OFFB); // 4
    transpose_kernel<<<dim3(64 * 64 / 32, 8, 2), tblk>>>(x1, OFF_X1N, 64 * 64); // 5
    mdconv_mma_kernel<<<dim3(128 * 128 / 64, 2), 256, MD_SMEM_BYTES>>>(         // 6
        OFF_X0N, 128, 128, OFF_OFFB, 128, 128, 1, 1, OFF_W3MID, OFF_YMID, 128 * 128, 128);
    reorder_w_tf32_kernel<<<2304, 256>>>(w_low,  OFF_W3LOW);                    // 7
    reorder_w_tf32_kernel<<<2304, 256>>>(w_high, OFF_W3HIGH);                   // 8
    transpose_kernel<<<dim3(32 * 32 / 32, 8, 2), tblk>>>(x2, OFF_X2N, 32 * 32); // 9

    const int Hs[3] = {128, 64, 32};
    const size_t xn_offs[3] = {OFF_X0N, OFF_X1N, OFF_X2N};
    size_t outoff = 0;

    for (int l = 0; l < 3; ++l) {
        int H = Hs[l], HW = H * H;
        int hasLow = (l > 0), hasHigh = (l < 2);
        int nbr = 1 + hasLow + hasHigh;

        if (l > 0) {
            offconv_kernel<<<dim3(HW / 128, 2), 256>>>(xn_offs[l], H, H, OFF_W3OFF, b_off, OFF_OFFB);
            mdconv_mma_kernel<<<dim3(HW / 64, 2), 256, MD_SMEM_BYTES>>>(
                xn_offs[l], H, H, OFF_OFFB, H, H, 1, 1, OFF_W3MID, OFF_YMID, HW, H);
        }
        chan_stats_kernel<<<dim3(256, 2), 256>>>(OFF_YMID, HW, OFF_CHSUM, OFF_CHSQ);
        gn_finalize_kernel<<<2, 256>>>(OFF_CHSUM, OFF_CHSQ, g_mid, be_mid, w_sa, b_sa,
                                       1.f / HW, 1.f / (16.f * HW),
                                       OFF_GNM, OFF_GNR, OFF_SV);
        if (hasLow) {
            int Hi = Hs[l - 1];
            mdconv_mma_kernel<<<dim3(HW / 64, 2), 256, MD_SMEM_BYTES>>>(
                xn_offs[l - 1], Hi, Hi, OFF_OFFB, H, H, 1, 2, OFF_W3LOW, OFF_YLOW, HW, H);
            chan_stats_kernel<<<dim3(256, 2), 256>>>(OFF_YLOW, HW, OFF_CHSUM, OFF_CHSQ);
            gn_finalize_kernel<<<2, 256>>>(OFF_CHSUM, OFF_CHSQ, g_low, be_low, w_sa, b_sa,
                                           1.f / HW, 1.f / (16.f * HW),
                                           OFF_GNM + 32, OFF_GNR + 32, OFF_SV + 2);
        }
        int Hh = H / 2, HWh = Hh * Hh;
        if (hasHigh) {
            mdconv_mma_kernel<<<dim3(HWh / 64, 2), 256, MD_SMEM_BYTES>>>(
                xn_offs[l + 1], Hh, Hh, OFF_OFFB, H, H, 2, 1, OFF_W3HIGH, OFF_YHIGH, HWh, Hh);
            chan_stats_kernel<<<dim3(256, 2), 256>>>(OFF_YHIGH, HWh, OFF_CHSUM, OFF_CHSQ);
            gn_finalize_kernel<<<2, 256>>>(OFF_CHSUM, OFF_CHSQ, g_high, be_high, w_sa, b_sa,
                                           1.f / HWh, 1.f / (16.f * HWh),
                                           OFF_GNM + 64, OFF_GNR + 64, OFF_SV + 4);
        }

        zero_kernel<<<2, 256>>>(OFF_P2, 512);
        float ry = (float)(Hh - 1) / (float)(H - 1);
        combine_kernel<<<dim3(HW / 256, 256, 2), 256>>>(
            OFF_YMID, OFF_YLOW, OFF_YHIGH, hasLow, hasHigh,
            H, HW, Hh, Hh, ry, ry,
            OFF_GNM, OFF_GNR, OFF_SV,
            g_mid, be_mid, g_low, be_low, g_high, be_high,
            1.f / (float)nbr, OFF_SUMF, OFF_P2);

        dycoef_kernel<<<2, 1024>>>(OFF_P2, 1.f / HW, w_dy1, b_dy1, w_dy2, b_dy2, OFF_COEF);

        int total = 2 * 256 * HW;
        dyrelu_kernel<<<total / 256, 256>>>(OFF_SUMF, OFF_COEF, HW, out + outoff, 256 * HW);
        outoff += (size_t)total;
    }
}

// round 5
// speedup vs baseline: 2.3238x; 1.4334x over previous
#include <cuda_runtime.h>
#include <cuda_fp16.h>
#include <math.h>
#include <stdint.h>

// ---------------------------------------------------------------------------
// DyHead-style MultiAttentionBlock. FP16 tensor-core mdconv + offconv.
// B=2, C=256, levels H = {128, 64, 32}, GN groups = 16.
// ---------------------------------------------------------------------------

constexpr int BN = 2;
constexpr int C  = 256;

// ---- scratch layout (floats) ----
constexpr size_t OFF_X0N   = 0;
constexpr size_t OFF_X1N   = OFF_X0N  + (size_t)BN*128*128*C;
constexpr size_t OFF_X2N   = OFF_X1N  + (size_t)BN*64*64*C;
constexpr size_t OFF_OFFB  = OFF_X2N  + (size_t)BN*32*32*C;
constexpr size_t OFF_YMID  = OFF_OFFB + (size_t)BN*128*128*27;
constexpr size_t OFF_YLOW  = OFF_YMID + (size_t)BN*C*128*128;
constexpr size_t OFF_YHIGH = OFF_YLOW + (size_t)BN*C*64*64;
constexpr size_t OFF_SUMF  = OFF_YHIGH+ (size_t)BN*C*64*64;
constexpr size_t OFF_W3MID = OFF_SUMF + (size_t)BN*C*128*128;   // half[9*256*256]
constexpr size_t OFF_W3LOW = OFF_W3MID + (size_t)9*256*256;
constexpr size_t OFF_W3HIGH= OFF_W3LOW + (size_t)9*256*256;
constexpr size_t OFF_W3OFF = OFF_W3HIGH+ (size_t)9*256*256;     // half[9*32*256]
constexpr size_t OFF_STAT  = OFF_W3OFF + (size_t)9*256*32;      // 3 sets x (512 sum + 512 sq)
constexpr size_t OFF_GNM   = OFF_STAT  + 3072;
constexpr size_t OFF_GNR   = OFF_GNM   + 96;
constexpr size_t OFF_SV    = OFF_GNR   + 96;
constexpr size_t OFF_P2    = OFF_SV    + 8;
constexpr size_t OFF_COEF  = OFF_P2    + 512;
constexpr size_t SCRATCH_TOTAL = OFF_COEF + 2048;

__device__ __align__(256) float g_scratch[SCRATCH_TOTAL];

// mdconv dynamic smem (bytes):
//   Ash : half [2][64*40]   at 0      (10240 B)
//   Bsh : half [2][256*40]  at 10240  (40960 B)
//   swt9: float[9*256]      at 51200  (9216 B)
//   sb9 : int  [9*256]      at 60416  (9216 B)
constexpr int MD_SMEM_BYTES = 69632;

__device__ __forceinline__ void mma_f16(float* d, const uint32_t* a, uint32_t b0, uint32_t b1) {
    asm volatile(
        "mma.sync.aligned.m16n8k16.row.col.f32.f16.f16.f32 "
        "{%0,%1,%2,%3},{%4,%5,%6,%7},{%8,%9},{%0,%1,%2,%3};\n"
        : "+f"(d[0]), "+f"(d[1]), "+f"(d[2]), "+f"(d[3])
        : "r"(a[0]), "r"(a[1]), "r"(a[2]), "r"(a[3]), "r"(b0), "r"(b1));
}

__device__ __forceinline__ void cp_async16(uint32_t daddr, const void* src) {
    asm volatile("cp.async.cg.shared.global [%0], [%1], 16;\n" :: "r"(daddr), "l"(src));
}

// ---------------------------------------------------------------------------
// prep: w_mid -> half [k][o][c], w_off -> half [k][o32][c], zero stat buffers.
// ---------------------------------------------------------------------------
__global__ void prep_kernel(const float* __restrict__ w_mid, const float* __restrict__ w_off) {
    int bidx = blockIdx.x;
    if (bidx < 2304) {
        int idx = bidx * 256 + threadIdx.x;           // < 9*256*256
        int k = idx >> 16, o = (idx >> 8) & 255, c = idx & 255;
        ((half*)(g_scratch + OFF_W3MID))[idx] = __float2half(w_mid[(o * 256 + c) * 9 + k]);
    } else if (bidx < 2592) {
        int idx = (bidx - 2304) * 256 + threadIdx.x;  // < 9*32*256
        int k = idx >> 13, o = (idx >> 8) & 31, c = idx & 255;
        ((half*)(g_scratch + OFF_W3OFF))[idx] =
            __float2half(o < 27 ? w_off[(o * 256 + c) * 9 + k] : 0.f);
    } else {
        int idx = (bidx - 2592) * 256 + threadIdx.x;
        if (idx < 3072) g_scratch[OFF_STAT + idx] = 0.f;
    }
}

__global__ void reorder_w_half_kernel(const float* __restrict__ w, size_t out_o) {
    int idx = blockIdx.x * 256 + threadIdx.x;         // < 9*256*256
    int k = idx >> 16, o = (idx >> 8) & 255, c = idx & 255;
    ((half*)(g_scratch + out_o))[idx] = __float2half(w[(o * 256 + c) * 9 + k]);
}

// ---------------------------------------------------------------------------
// NCHW -> NHWC transpose.
// ---------------------------------------------------------------------------
__global__ void transpose_kernel(const float* __restrict__ in, size_t out_o, int HW) {
    __shared__ float t[32][33];
    int b = blockIdx.z;
    int hw0 = blockIdx.x * 32, c0 = blockIdx.y * 32;
    int tx = threadIdx.x, ty = threadIdx.y;  // 32 x 8
    #pragma unroll
    for (int i = 0; i < 32; i += 8)
        t[ty + i][tx] = in[((size_t)b * C + c0 + ty + i) * HW + hw0 + tx];
    __syncthreads();
    #pragma unroll
    for (int i = 0; i < 32; i += 8)
        g_scratch[out_o + ((size_t)b * HW + hw0 + ty + i) * C + c0 + tx] = t[tx][ty + i];
}

// ---------------------------------------------------------------------------
// Offset conv via fp16 MMA. 3x3, 256 -> 27 (padded 32), zero-pad im2col.
// Block: 128 px x 32 o, 256 threads (8 warps = 4M x 2N).
// ---------------------------------------------------------------------------
__global__ __launch_bounds__(256) void offconv_mma_kernel(
    size_t xn_o, int H, int W,
    const float* __restrict__ bias, size_t out_o)
{
    __shared__ half Ash[2][128 * 40];
    __shared__ half Bsh[2][32 * 40];

    int b = blockIdx.y, tile = blockIdx.x, tid = threadIdx.x;
    int lane = tid & 31, warp = tid >> 5;
    int warpM = warp >> 1, warpN = warp & 1;
    const float* xn = g_scratch + xn_o;
    const half* wh = (const half*)(g_scratch + OFF_W3OFF);

    float acc[2][2][4];
    #pragma unroll
    for (int mt = 0; mt < 2; ++mt)
        #pragma unroll
        for (int nt = 0; nt < 2; ++nt)
            #pragma unroll
            for (int r = 0; r < 4; ++r) acc[mt][nt][r] = 0.f;

    int tpx = tid >> 1, tseg = tid & 1;
    int p = tile * 128 + tpx;
    int ph = p / W, pw = p - ph * W;

    uint32_t bs_saddr = (uint32_t)__cvta_generic_to_shared(&Bsh[0][0]);

    float4 gr[4];
    auto gather_ldg = [&](int s) {
        int k = s >> 3, c0 = (s & 7) << 5;
        int dy = k / 3 - 1, dx = k % 3 - 1;
        int y = ph + dy, x = pw + dx;
        bool valid = (y >= 0 && y < H && x >= 0 && x < W);
        const float* src = xn + ((size_t)(b * H + y) * W + x) * 256 + c0 + tseg * 16;
        #pragma unroll
        for (int i = 0; i < 4; ++i)
            gr[i] = valid ? *(const float4*)(src + i * 4) : make_float4(0.f, 0.f, 0.f, 0.f);
    };
    auto sts_a = [&](int buf) {
        half* dst = &Ash[buf][tpx * 40 + tseg * 16];
        #pragma unroll
        for (int i = 0; i < 4; ++i) {
            *(half2*)&dst[i * 4]     = __floats2half2_rn(gr[i].x, gr[i].y);
            *(half2*)&dst[i * 4 + 2] = __floats2half2_rn(gr[i].z, gr[i].w);
        }
    };
    auto cpasync_b = [&](int s, int buf) {
        int k = s >> 3, c0 = (s & 7) << 5;
        if (tid < 128) {
            int o = tid >> 2, seg = tid & 3;
            cp_async16(bs_saddr + (uint32_t)(buf * 2560 + o * 80 + seg * 16),
                       wh + ((size_t)(k * 32 + o) << 8) + c0 + seg * 8);
        }
        asm volatile("cp.async.commit_group;\n");
    };

    gather_ldg(0);
    cpasync_b(0, 0);

    for (int s = 0; s < 72; ++s) {
        int cb = s & 1;
        sts_a(cb);
        if (s < 71) gather_ldg(s + 1);
        asm volatile("cp.async.wait_group 0;\n");
        __syncthreads();
        if (s < 71) cpasync_b(s + 1, cb ^ 1);

        const half* Ab = Ash[cb];
        const half* Bb = Bsh[cb];
        #pragma unroll
        for (int ks = 0; ks < 2; ++ks) {
            int kb = ks * 16 + 2 * (lane & 3);
            int arow = warpM * 32 + (lane >> 2);
            uint32_t a[2][4];
            #pragma unroll
            for (int mt = 0; mt < 2; ++mt) {
                a[mt][0] = *(const uint32_t*)&Ab[(arow + mt * 16) * 40 + kb];
                a[mt][1] = *(const uint32_t*)&Ab[(arow + mt * 16 + 8) * 40 + kb];
                a[mt][2] = *(const uint32_t*)&Ab[(arow + mt * 16) * 40 + kb + 8];
                a[mt][3] = *(const uint32_t*)&Ab[(arow + mt * 16 + 8) * 40 + kb + 8];
            }
            int bo = warpN * 16 + (lane >> 2);
            #pragma unroll
            for (int nt = 0; nt < 2; ++nt) {
                uint32_t b0 = *(const uint32_t*)&Bb[(bo + nt * 8) * 40 + kb];
                uint32_t b1 = *(const uint32_t*)&Bb[(bo + nt * 8) * 40 + kb + 8];
                mma_f16(acc[0][nt], a[0], b0, b1);
                mma_f16(acc[1][nt], a[1], b0, b1);
            }
        }
        __syncthreads();
    }

    // epilogue: [b][px][27]
    int HWl = H * W;
    int pxb = tile * 128 + warpM * 32 + (lane >> 2);
    #pragma unroll
    for (int nt = 0; nt < 2; ++nt) {
        int o = warpN * 16 + nt * 8 + 2 * (lane & 3);
        float bv0 = (o < 27) ? bias[o] : 0.f;
        float bv1 = (o + 1 < 27) ? bias[o + 1] : 0.f;
        #pragma unroll
        for (int mt = 0; mt < 2; ++mt) {
            #pragma unroll
            for (int rr = 0; rr < 2; ++rr) {
                int px = pxb + mt * 16 + rr * 8;
                float v0 = acc[mt][nt][rr * 2 + 0] + bv0;
                float v1 = acc[mt][nt][rr * 2 + 1] + bv1;
                size_t ob = out_o + ((size_t)b * HWl + px) * 27;
                if (o < 27) {
                    if (o >= 18) v0 = 1.f / (1.f + expf(-v0));
                    g_scratch[ob + o] = v0;
                }
                if (o + 1 < 27) {
                    if (o + 1 >= 18) v1 = 1.f / (1.f + expf(-v1));
                    g_scratch[ob + o + 1] = v1;
                }
            }
        }
    }
}

// ---------------------------------------------------------------------------
// Modulated deformable conv: fused bilinear gather + FP16 MMA, pipelined,
// with fused per-(b,c) sum/sumsq stats (atomics).
// Block: 64 px x 256 o, 256 threads (8 warps = 2M x 4N). 72 chunks of 32 c.
// ---------------------------------------------------------------------------
__global__ __launch_bounds__(256) void mdconv_mma_kernel(
    size_t xn_o, int Hi, int Wi,
    size_t off_o, int offH, int offW, int offmul,
    int stride, size_t w3_o,
    size_t y_o, int HWo, int Wo, size_t stat_o)
{
    extern __shared__ char smraw[];
    half*  Ash  = (half*)smraw;               // [2][64*40]
    half*  Bsh  = (half*)(smraw + 10240);     // [2][256*40]
    float* swt9 = (float*)(smraw + 51200);    // [9*256]
    int*   sb9  = (int*)(smraw + 60416);      // [9*256]

    int b = blockIdx.y, tile = blockIdx.x, tid = threadIdx.x;
    int lane = tid & 31, warp = tid >> 5;
    int warpM = warp & 1, warpN = warp >> 1;

    const float* xn = g_scratch + xn_o;
    const half* w3h = (const half*)(g_scratch + w3_o);

    // precompute gather tables for all 9 taps
    for (int it = tid; it < 576; it += 256) {
        int k = it >> 6, p = it & 63;
        int pg = tile * 64 + p;
        int h = pg / Wo, w = pg - h * Wo;
        size_t ob = off_o + ((size_t)(b * offH + h * offmul) * offW + w * offmul) * 27;
        float oy = g_scratch[ob + 2 * k];
        float ox = g_scratch[ob + 2 * k + 1];
        float m  = g_scratch[ob + 18 + k];
        float py  = (float)(h * stride - 1 + k / 3) + oy;
        float pxx = (float)(w * stride - 1 + k % 3) + ox;
        float fy = floorf(py), fx = floorf(pxx);
        int y0 = (int)fy, x0 = (int)fx;
        float wy = py - fy, wx = pxx - fx;
        int y1 = y0 + 1, x1 = x0 + 1;
        float vy0 = (y0 >= 0 && y0 < Hi) ? 1.f : 0.f;
        float vy1 = (y1 >= 0 && y1 < Hi) ? 1.f : 0.f;
        float vx0 = (x0 >= 0 && x0 < Wi) ? 1.f : 0.f;
        float vx1 = (x1 >= 0 && x1 < Wi) ? 1.f : 0.f;
        int y0c = min(max(y0, 0), Hi - 1), y1c = min(max(y1, 0), Hi - 1);
        int x0c = min(max(x0, 0), Wi - 1), x1c = min(max(x1, 0), Wi - 1);
        int kb = k * 256 + p;
        swt9[kb]       = (1.f - wy) * (1.f - wx) * m * vy0 * vx0;
        swt9[kb + 64]  = (1.f - wy) * wx * m * vy0 * vx1;
        swt9[kb + 128] = wy * (1.f - wx) * m * vy1 * vx0;
        swt9[kb + 192] = wy * wx * m * vy1 * vx1;
        sb9[kb]       = ((b * Hi + y0c) * Wi + x0c) * 256;
        sb9[kb + 64]  = ((b * Hi + y0c) * Wi + x1c) * 256;
        sb9[kb + 128] = ((b * Hi + y1c) * Wi + x0c) * 256;
        sb9[kb + 192] = ((b * Hi + y1c) * Wi + x1c) * 256;
    }
    __syncthreads();

    float acc[2][8][4];
    #pragma unroll
    for (int mt = 0; mt < 2; ++mt)
        #pragma unroll
        for (int nt = 0; nt < 8; ++nt)
            #pragma unroll
            for (int r = 0; r < 4; ++r) acc[mt][nt][r] = 0.f;

    int gpx = tid & 63;
    int gcq = tid >> 6;   // 0..3

    uint32_t bs_saddr = (uint32_t)__cvta_generic_to_shared(Bsh);

    float gw0, gw1, gw2, gw3;
    float4 gv0[2], gv1[2], gv2[2], gv3[2];

    auto gather_ldg = [&](int s) {
        int kk = s >> 3, c0n = (s & 7) << 5;
        int kb = kk * 256 + gpx;
        gw0 = swt9[kb]; gw1 = swt9[kb + 64]; gw2 = swt9[kb + 128]; gw3 = swt9[kb + 192];
        int b00 = sb9[kb], b01 = sb9[kb + 64], b10 = sb9[kb + 128], b11 = sb9[kb + 192];
        #pragma unroll
        for (int it = 0; it < 2; ++it) {
            int cofs = c0n + (gcq + it * 4) * 4;
            gv0[it] = *(const float4*)(xn + b00 + cofs);
            gv1[it] = *(const float4*)(xn + b01 + cofs);
            gv2[it] = *(const float4*)(xn + b10 + cofs);
            gv3[it] = *(const float4*)(xn + b11 + cofs);
        }
    };
    auto combine_sts = [&](int buf) {
        half* dst = Ash + buf * 2560 + gpx * 40;
        #pragma unroll
        for (int it = 0; it < 2; ++it) {
            int cq = gcq + it * 4;
            float f0 = gw0 * gv0[it].x + gw1 * gv1[it].x + gw2 * gv2[it].x + gw3 * gv3[it].x;
            float f1 = gw0 * gv0[it].y + gw1 * gv1[it].y + gw2 * gv2[it].y + gw3 * gv3[it].y;
            float f2 = gw0 * gv0[it].z + gw1 * gv1[it].z + gw2 * gv2[it].z + gw3 * gv3[it].z;
            float f3 = gw0 * gv0[it].w + gw1 * gv1[it].w + gw2 * gv2[it].w + gw3 * gv3[it].w;
            *(half2*)&dst[cq * 4]     = __floats2half2_rn(f0, f1);
            *(half2*)&dst[cq * 4 + 2] = __floats2half2_rn(f2, f3);
        }
    };
    auto cpasync_b = [&](int s, int buf) {
        int kk = s >> 3, c0n = (s & 7) << 5;
        const half* wsrc = w3h + ((size_t)kk << 16) + c0n;   // [k][o][c], row = 256 halves
        #pragma unroll
        for (int it = 0; it < 4; ++it) {
            int e = it * 256 + tid;
            int o = e >> 2, seg = e & 3;
            cp_async16(bs_saddr + (uint32_t)(buf * 20480 + o * 80 + seg * 16),
                       wsrc + o * 256 + seg * 8);
        }
        asm volatile("cp.async.commit_group;\n");
    };

    gather_ldg(0);
    cpasync_b(0, 0);

    for (int s = 0; s < 72; ++s) {
        int cb = s & 1;
        combine_sts(cb);
        if (s < 71) gather_ldg(s + 1);
        asm volatile("cp.async.wait_group 0;\n");
        __syncthreads();
        if (s < 71) cpasync_b(s + 1, cb ^ 1);

        const half* Ab = Ash + cb * 2560;
        const half* Bb = Bsh + cb * 10240;
        #pragma unroll
        for (int ks = 0; ks < 2; ++ks) {
            int kb = ks * 16 + 2 * (lane & 3);
            int arow = warpM * 32 + (lane >> 2);
            uint32_t a[2][4];
            #pragma unroll
            for (int mt = 0; mt < 2; ++mt) {
                a[mt][0] = *(const uint32_t*)&Ab[(arow + mt * 16) * 40 + kb];
                a[mt][1] = *(const uint32_t*)&Ab[(arow + mt * 16 + 8) * 40 + kb];
                a[mt][2] = *(const uint32_t*)&Ab[(arow + mt * 16) * 40 + kb + 8];
                a[mt][3] = *(const uint32_t*)&Ab[(arow + mt * 16 + 8) * 40 + kb + 8];
            }
            int bo = warpN * 64 + (lane >> 2);
            #pragma unroll
            for (int nt = 0; nt < 8; ++nt) {
                uint32_t b0 = *(const uint32_t*)&Bb[(bo + nt * 8) * 40 + kb];
                uint32_t b1 = *(const uint32_t*)&Bb[(bo + nt * 8) * 40 + kb + 8];
                mma_f16(acc[0][nt], a[0], b0, b1);
                mma_f16(acc[1][nt], a[1], b0, b1);
            }
        }
        __syncthreads();
    }

    // epilogue: Y [b][o][HWo] + fused stats
    float* yp = g_scratch + y_o + (size_t)b * 256 * HWo;
    float* st_sum = g_scratch + stat_o + b * 256;
    float* st_sq  = g_scratch + stat_o + 512 + b * 256;
    int px0 = tile * 64 + warpM * 32 + (lane >> 2);
    #pragma unroll
    for (int nt = 0; nt < 8; ++nt) {
        int o = warpN * 64 + nt * 8 + 2 * (lane & 3);
        float s0 = 0.f, s1 = 0.f, q0 = 0.f, q1 = 0.f;
        #pragma unroll
        for (int mt = 0; mt < 2; ++mt) {
            int px = px0 + mt * 16;
            float v0 = acc[mt][nt][0], v1 = acc[mt][nt][1];
            float v2 = acc[mt][nt][2], v3 = acc[mt][nt][3];
            yp[(size_t)o * HWo + px]           = v0;
            yp[(size_t)(o + 1) * HWo + px]     = v1;
            yp[(size_t)o * HWo + px + 8]       = v2;
            yp[(size_t)(o + 1) * HWo + px + 8] = v3;
            s0 += v0 + v2; s1 += v1 + v3;
            q0 += v0 * v0 + v2 * v2; q1 += v1 * v1 + v3 * v3;
        }
        #pragma unroll
        for (int off = 16; off >= 4; off >>= 1) {
            s0 += __shfl_down_sync(0xffffffffu, s0, off);
            s1 += __shfl_down_sync(0xffffffffu, s1, off);
            q0 += __shfl_down_sync(0xffffffffu, q0, off);
            q1 += __shfl_down_sync(0xffffffffu, q1, off);
        }
        if (lane < 4) {
            atomicAdd(&st_sum[o], s0);
            atomicAdd(&st_sum[o + 1], s1);
            atomicAdd(&st_sq[o], q0);
            atomicAdd(&st_sq[o + 1], q1);
        }
    }
}

// ---------------------------------------------------------------------------
// GN finalize + scale-attn scalar (analytic pooled value).
// ---------------------------------------------------------------------------
__global__ void gn_finalize_kernel(
    size_t sum_o, size_t sq_o,
    const float* __restrict__ gamma, const float* __restrict__ beta,
    const float* __restrict__ w_sa, const float* __restrict__ b_sa,
    float inv_hw, float inv_cnt,
    size_t gnm_o, size_t gnr_o, size_t sv_o)
{
    int b = blockIdx.x, t = threadIdx.x;  // 256
    __shared__ float ss[256], qq[256], gm[16], gr[16], red[256];
    ss[t] = g_scratch[sum_o + b * 256 + t];
    qq[t] = g_scratch[sq_o + b * 256 + t];
    __syncthreads();
    if (t < 16) {
        float S = 0.f, Q = 0.f;
        #pragma unroll
        for (int j = 0; j < 16; ++j) { S += ss[t * 16 + j]; Q += qq[t * 16 + j]; }
        float mean = S * inv_cnt;
        float var = Q * inv_cnt - mean * mean;
        float r = rsqrtf(var + 1e-5f);
        gm[t] = mean; gr[t] = r;
        g_scratch[gnm_o + b * 16 + t] = mean;
        g_scratch[gnr_o + b * 16 + t] = r;
    }
    __syncthreads();
    int g = t >> 4;
    float p = gamma[t] * (ss[t] * inv_hw - gm[g]) * gr[g] + beta[t];
    red[t] = p * w_sa[t];
    __syncthreads();
    for (int off = 128; off; off >>= 1) {
        if (t < off) red[t] += red[t + off];
        __syncthreads();
    }
    if (t == 0) {
        float x = fmaxf(red[0] + b_sa[0], 0.f);
        g_scratch[sv_o + b] = fminf(x + 3.f, 6.f) * (1.f / 6.f);
    }
}

__global__ void zero_kernel(size_t o, int n) {
    int i = blockIdx.x * 256 + threadIdx.x;
    if (i < n) g_scratch[o + i] = 0.f;
}

// ---------------------------------------------------------------------------
// Combine branches + pooled sums.
// ---------------------------------------------------------------------------
__global__ void combine_kernel(
    size_t ymid_o, size_t ylow_o, size_t yhigh_o,
    int hasLow, int hasHigh, int W, int HW, int Hh, int Wh, float ry, float rx,
    size_t gnm_o, size_t gnr_o, size_t sv_o,
    const float* __restrict__ gw_mid, const float* __restrict__ gb_mid,
    const float* __restrict__ gw_low, const float* __restrict__ gb_low,
    const float* __restrict__ gw_high, const float* __restrict__ gb_high,
    float inv_n, size_t sumf_o, size_t p2_o)
{
    int b = blockIdx.z, c = blockIdx.y;
    int px = blockIdx.x * 256 + threadIdx.x;
    int g = c >> 4;
    int gi = b * 16 + g;
    size_t base = ((size_t)(b * 256 + c)) * HW;

    float v = g_scratch[sv_o + b] *
              (gw_mid[c] * (g_scratch[ymid_o + base + px] - g_scratch[gnm_o + gi]) * g_scratch[gnr_o + gi] + gb_mid[c]);
    if (hasLow)
        v += g_scratch[sv_o + 2 + b] *
             (gw_low[c] * (g_scratch[ylow_o + base + px] - g_scratch[gnm_o + 32 + gi]) * g_scratch[gnr_o + 32 + gi] + gb_low[c]);
    if (hasHigh) {
        int h = px / W, w = px - h * W;
        float sy = h * ry, sx = w * rx;
        int yl = (int)sy; int yh2 = min(yl + 1, Hh - 1);
        int xl = (int)sx; int xh = min(xl + 1, Wh - 1);
        float wy = sy - (float)yl, wx = sx - (float)xl;
        const float* hp = g_scratch + yhigh_o + ((size_t)(b * 256 + c)) * Hh * Wh;
        float t0 = hp[yl * Wh + xl] * (1.f - wx) + hp[yl * Wh + xh] * wx;
        float t1 = hp[yh2 * Wh + xl] * (1.f - wx) + hp[yh2 * Wh + xh] * wx;
        float raw = t0 * (1.f - wy) + t1 * wy;
        v += g_scratch[sv_o + 4 + b] *
             (gw_high[c] * (raw - g_scratch[gnm_o + 64 + gi]) * g_scratch[gnr_o + 64 + gi] + gb_high[c]);
    }
    v *= inv_n;
    g_scratch[sumf_o + base + px] = v;

    float r = v;
    #pragma unroll
    for (int o = 16; o; o >>= 1) r += __shfl_down_sync(0xffffffffu, r, o);
    __shared__ float wsum[8];
    if ((threadIdx.x & 31) == 0) wsum[threadIdx.x >> 5] = r;
    __syncthreads();
    if (threadIdx.x == 0) {
        float tt = 0.f;
        #pragma unroll
        for (int i = 0; i < 8; ++i) tt += wsum[i];
        atomicAdd(&g_scratch[p2_o + b * 256 + c], tt);
    }
}

// ---------------------------------------------------------------------------
// DyReLU coefficients.
// ---------------------------------------------------------------------------
__global__ void dycoef_kernel(size_t p2_o, float inv_hw,
    const float* __restrict__ w1, const float* __restrict__ b1,
    const float* __restrict__ w2, const float* __restrict__ b2,
    size_t coef_o)
{
    int b = blockIdx.x, t = threadIdx.x;  // 1024
    __shared__ float pm[256], hb[64];
    if (t < 256) pm[t] = g_scratch[p2_o + b * 256 + t] * inv_hw;
    __syncthreads();
    if (t < 64) {
        float a = b1[t];
        for (int cx = 0; cx < 256; ++cx) a += pm[cx] * w1[t * 256 + cx];
        hb[t] = fmaxf(a, 0.f);
    }
    __syncthreads();
    float a = b2[t];
    #pragma unroll
    for (int i = 0; i < 64; ++i) a += hb[i] * w2[t * 64 + i];
    float hs = fminf(fmaxf(a + 3.f, 0.f), 6.f) * (1.f / 6.f);
    g_scratch[coef_o + b * 1024 + t] = hs - 0.5f;
}

// ---------------------------------------------------------------------------
// Apply DyReLU, write final output.
// ---------------------------------------------------------------------------
__global__ void dyrelu_kernel(size_t sumf_o, size_t coef_o, int HW, float* __restrict__ outp, int CHW) {
    int idx = blockIdx.x * 256 + threadIdx.x;
    int b = idx / CHW;
    int c = (idx - b * CHW) / HW;
    const float* cf = g_scratch + coef_o + b * 1024;
    float x = g_scratch[sumf_o + idx];
    float a1 = cf[c] * 2.f + 1.f, bb1 = cf[256 + c];
    float a2 = cf[512 + c] * 2.f, bb2 = cf[768 + c];
    outp[idx] = fmaxf(x * a1 + bb1, x * a2 + bb2);
}

// ---------------------------------------------------------------------------
// Host orchestration
// ---------------------------------------------------------------------------
extern "C" void kernel_launch(void* const* d_in, const int* in_sizes, int n_in,
                              void* d_out, int out_size) {
    (void)in_sizes; (void)n_in; (void)out_size;
    const float* x0     = (const float*)d_in[0];
    const float* x1     = (const float*)d_in[1];
    const float* x2     = (const float*)d_in[2];
    const float* w_off  = (const float*)d_in[3];
    const float* b_off  = (const float*)d_in[4];
    const float* w_mid  = (const float*)d_in[5];
    const float* g_mid  = (const float*)d_in[6];
    const float* be_mid = (const float*)d_in[7];
    const float* w_low  = (const float*)d_in[8];
    const float* g_low  = (const float*)d_in[9];
    const float* be_low = (const float*)d_in[10];
    const float* w_high = (const float*)d_in[11];
    const float* g_high = (const float*)d_in[12];
    const float* be_high= (const float*)d_in[13];
    const float* w_sa   = (const float*)d_in[14];
    const float* b_sa   = (const float*)d_in[15];
    const float* w_dy1  = (const float*)d_in[16];
    const float* b_dy1  = (const float*)d_in[17];
    const float* w_dy2  = (const float*)d_in[18];
    const float* b_dy2  = (const float*)d_in[19];
    float* out = (float*)d_out;

    static bool attr_set = false;
    if (!attr_set) {
        cudaFuncSetAttribute(mdconv_mma_kernel,
                             cudaFuncAttributeMaxDynamicSharedMemorySize, MD_SMEM_BYTES);
        attr_set = true;
    }

    dim3 tblk(32, 8);
    const int Hs[3] = {128, 64, 32};
    const size_t xn_offs[3] = {OFF_X0N, OFF_X1N, OFF_X2N};

    // Launch order: slot 4 = mdconv mid L0 for the ncu window.
    transpose_kernel<<<dim3(128 * 128 / 32, 8, 2), tblk>>>(x0, OFF_X0N, 128 * 128);   // 1
    prep_kernel<<<2604, 256>>>(w_mid, w_off);                                          // 2
    offconv_mma_kernel<<<dim3(128 * 128 / 128, 2), 256>>>(OFF_X0N, 128, 128, b_off, OFF_OFFB); // 3
    mdconv_mma_kernel<<<dim3(128 * 128 / 64, 2), 256, MD_SMEM_BYTES>>>(                // 4
        OFF_X0N, 128, 128, OFF_OFFB, 128, 128, 1, 1, OFF_W3MID, OFF_YMID, 128 * 128, 128, OFF_STAT);
    reorder_w_half_kernel<<<2304, 256>>>(w_low,  OFF_W3LOW);                           // 5
    reorder_w_half_kernel<<<2304, 256>>>(w_high, OFF_W3HIGH);                          // 6
    transpose_kernel<<<dim3(64 * 64 / 32, 8, 2), tblk>>>(x1, OFF_X1N, 64 * 64);        // 7
    transpose_kernel<<<dim3(32 * 32 / 32, 8, 2), tblk>>>(x2, OFF_X2N, 32 * 32);        // 8

    size_t outoff = 0;
    for (int l = 0; l < 3; ++l) {
        int H = Hs[l], HW = H * H;
        int hasLow = (l > 0), hasHigh = (l < 2);
        int nbr = 1 + hasLow + hasHigh;
        int Hh = H / 2, HWh = Hh * Hh;

        if (l > 0) {
            zero_kernel<<<12, 256>>>(OFF_STAT, 3072);
            offconv_mma_kernel<<<dim3(HW / 128, 2), 256>>>(xn_offs[l], H, H, b_off, OFF_OFFB);
            mdconv_mma_kernel<<<dim3(HW / 64, 2), 256, MD_SMEM_BYTES>>>(
                xn_offs[l], H, H, OFF_OFFB, H, H, 1, 1, OFF_W3MID, OFF_YMID, HW, H, OFF_STAT);
        }
        gn_finalize_kernel<<<2, 256>>>(OFF_STAT, OFF_STAT + 512, g_mid, be_mid, w_sa, b_sa,
                                       1.f / HW, 1.f / (16.f * HW),
                                       OFF_GNM, OFF_GNR, OFF_SV);
        if (hasLow) {
            int Hi = Hs[l - 1];
            mdconv_mma_kernel<<<dim3(HW / 64, 2), 256, MD_SMEM_BYTES>>>(
                xn_offs[l - 1], Hi, Hi, OFF_OFFB, H, H, 1, 2, OFF_W3LOW, OFF_YLOW, HW, H,
                OFF_STAT + 1024);
            gn_finalize_kernel<<<2, 256>>>(OFF_STAT + 1024, OFF_STAT + 1536, g_low, be_low, w_sa, b_sa,
                                           1.f / HW, 1.f / (16.f * HW),
                                           OFF_GNM + 32, OFF_GNR + 32, OFF_SV + 2);
        }
        if (hasHigh) {
            mdconv_mma_kernel<<<dim3(HWh / 64, 2), 256, MD_SMEM_BYTES>>>(
                xn_offs[l + 1], Hh, Hh, OFF_OFFB, H, H, 2, 1, OFF_W3HIGH, OFF_YHIGH, HWh, Hh,
                OFF_STAT + 2048);
            gn_finalize_kernel<<<2, 256>>>(OFF_STAT + 2048, OFF_STAT + 2560, g_high, be_high, w_sa, b_sa,
                                           1.f / HWh, 1.f / (16.f * HWh),
                                           OFF_GNM + 64, OFF_GNR + 64, OFF_SV + 4);
        }

        zero_kernel<<<2, 256>>>(OFF_P2, 512);
        float ry = (float)(Hh - 1) / (float)(H - 1);
        combine_kernel<<<dim3(HW / 256, 256, 2), 256>>>(
            OFF_YMID, OFF_YLOW, OFF_YHIGH, hasLow, hasHigh,
            H, HW, Hh, Hh, ry, ry,
            OFF_GNM, OFF_GNR, OFF_SV,
            g_mid, be_mid, g_low, be_low, g_high, be_high,
            1.f / (float)nbr, OFF_SUMF, OFF_P2);

        dycoef_kernel<<<2, 1024>>>(OFF_P2, 1.f / HW, w_dy1, b_dy1, w_dy2, b_dy2, OFF_COEF);

        int total = 2 * 256 * HW;
        dyrelu_kernel<<<total / 256, 256>>>(OFF_SUMF, OFF_COEF, HW, out + outoff, 256 * HW);
        outoff += (size_t)total;
    }
}

// round 6
// speedup vs baseline: 3.0784x; 1.3247x over previous
#include <cuda_runtime.h>
#include <cuda_fp16.h>
#include <math.h>
#include <stdint.h>

// ---------------------------------------------------------------------------
// DyHead-style MultiAttentionBlock. FP16 tensor-core mdconv + offconv,
// ldmatrix fragment loads, fp16 NHWC inputs.
// B=2, C=256, levels H = {128, 64, 32}, GN groups = 16.
// ---------------------------------------------------------------------------

constexpr int BN = 2;
constexpr int C  = 256;

// ---- scratch layout (float units; X buffers are half, occupy half the slot) ----
constexpr size_t OFF_X0N   = 0;
constexpr size_t OFF_X1N   = OFF_X0N  + (size_t)BN*128*128*C;
constexpr size_t OFF_X2N   = OFF_X1N  + (size_t)BN*64*64*C;
constexpr size_t OFF_OFFB  = OFF_X2N  + (size_t)BN*32*32*C;
constexpr size_t OFF_YMID  = OFF_OFFB + (size_t)BN*128*128*27;
constexpr size_t OFF_YLOW  = OFF_YMID + (size_t)BN*C*128*128;
constexpr size_t OFF_YHIGH = OFF_YLOW + (size_t)BN*C*64*64;
constexpr size_t OFF_SUMF  = OFF_YHIGH+ (size_t)BN*C*64*64;
constexpr size_t OFF_W3MID = OFF_SUMF + (size_t)BN*C*128*128;   // half[9*256*256]
constexpr size_t OFF_W3LOW = OFF_W3MID + (size_t)9*256*256;
constexpr size_t OFF_W3HIGH= OFF_W3LOW + (size_t)9*256*256;
constexpr size_t OFF_W3OFF = OFF_W3HIGH+ (size_t)9*256*256;     // half[9*32*256]
constexpr size_t OFF_STAT  = OFF_W3OFF + (size_t)9*256*32;      // 3 sets x (512 sum + 512 sq)
constexpr size_t OFF_GNM   = OFF_STAT  + 3072;
constexpr size_t OFF_GNR   = OFF_GNM   + 96;
constexpr size_t OFF_SV    = OFF_GNR   + 96;
constexpr size_t OFF_P2    = OFF_SV    + 8;
constexpr size_t OFF_COEF  = OFF_P2    + 512;
constexpr size_t SCRATCH_TOTAL = OFF_COEF + 2048;

__device__ __align__(256) float g_scratch[SCRATCH_TOTAL];

// mdconv dynamic smem (bytes):
//   Ash : half [2][64*40]   at 0      (10240 B)
//   Bsh : half [2][256*40]  at 10240  (40960 B)
//   swt9: float[9*256]      at 51200  (9216 B)
//   sb9 : int  [9*256]      at 60416  (9216 B)
constexpr int MD_SMEM_BYTES = 69632;

__device__ __forceinline__ void mma_f16(float* d, const uint32_t* a, uint32_t b0, uint32_t b1) {
    asm volatile(
        "mma.sync.aligned.m16n8k16.row.col.f32.f16.f16.f32 "
        "{%0,%1,%2,%3},{%4,%5,%6,%7},{%8,%9},{%0,%1,%2,%3};\n"
        : "+f"(d[0]), "+f"(d[1]), "+f"(d[2]), "+f"(d[3])
        : "r"(a[0]), "r"(a[1]), "r"(a[2]), "r"(a[3]), "r"(b0), "r"(b1));
}

__device__ __forceinline__ void ldsm_x4(uint32_t* r, const half* p) {
    uint32_t a = (uint32_t)__cvta_generic_to_shared(p);
    asm volatile("ldmatrix.sync.aligned.m8n8.x4.shared.b16 {%0,%1,%2,%3}, [%4];"
        : "=r"(r[0]), "=r"(r[1]), "=r"(r[2]), "=r"(r[3]) : "r"(a));
}

__device__ __forceinline__ void cp_async16(uint32_t daddr, const void* src) {
    asm volatile("cp.async.cg.shared.global [%0], [%1], 16;\n" :: "r"(daddr), "l"(src));
}

// ---------------------------------------------------------------------------
// prep: w_mid -> half [k][o][c], w_off -> half [k][o32][c], zero stat buffers.
// ---------------------------------------------------------------------------
__global__ void prep_kernel(const float* __restrict__ w_mid, const float* __restrict__ w_off) {
    int bidx = blockIdx.x;
    if (bidx < 2304) {
        int idx = bidx * 256 + threadIdx.x;           // < 9*256*256
        int k = idx >> 16, o = (idx >> 8) & 255, c = idx & 255;
        ((half*)(g_scratch + OFF_W3MID))[idx] = __float2half(w_mid[(o * 256 + c) * 9 + k]);
    } else if (bidx < 2592) {
        int idx = (bidx - 2304) * 256 + threadIdx.x;  // < 9*32*256
        int k = idx >> 13, o = (idx >> 8) & 31, c = idx & 255;
        ((half*)(g_scratch + OFF_W3OFF))[idx] =
            __float2half(o < 27 ? w_off[(o * 256 + c) * 9 + k] : 0.f);
    } else {
        int idx = (bidx - 2592) * 256 + threadIdx.x;
        if (idx < 3072) g_scratch[OFF_STAT + idx] = 0.f;
    }
}

__global__ void reorder_w_half_kernel(const float* __restrict__ w, size_t out_o) {
    int idx = blockIdx.x * 256 + threadIdx.x;         // < 9*256*256
    int k = idx >> 16, o = (idx >> 8) & 255, c = idx & 255;
    ((half*)(g_scratch + out_o))[idx] = __float2half(w[(o * 256 + c) * 9 + k]);
}

// ---------------------------------------------------------------------------
// NCHW fp32 -> NHWC fp16 transpose.
// ---------------------------------------------------------------------------
__global__ void transpose_kernel(const float* __restrict__ in, size_t out_o, int HW) {
    __shared__ float t[32][33];
    int b = blockIdx.z;
    int hw0 = blockIdx.x * 32, c0 = blockIdx.y * 32;
    int tx = threadIdx.x, ty = threadIdx.y;  // 32 x 8
    #pragma unroll
    for (int i = 0; i < 32; i += 8)
        t[ty + i][tx] = in[((size_t)b * C + c0 + ty + i) * HW + hw0 + tx];
    __syncthreads();
    half* xh = (half*)(g_scratch + out_o);
    #pragma unroll
    for (int i = 0; i < 32; i += 8)
        xh[((size_t)b * HW + hw0 + ty + i) * C + c0 + tx] = __float2half(t[tx][ty + i]);
}

// ---------------------------------------------------------------------------
// Offset conv via fp16 MMA + ldmatrix. 3x3, 256 -> 27 (padded 32).
// Block: 128 px x 32 o, 256 threads (8 warps = 4M x 2N).
// ---------------------------------------------------------------------------
__global__ __launch_bounds__(256) void offconv_mma_kernel(
    size_t xn_o, int H, int W,
    const float* __restrict__ bias, size_t out_o)
{
    __shared__ half Ash[2][128 * 40];
    __shared__ half Bsh[2][32 * 40];

    int b = blockIdx.y, tile = blockIdx.x, tid = threadIdx.x;
    int lane = tid & 31, warp = tid >> 5;
    int warpM = warp >> 1, warpN = warp & 1;
    const half* xn = (const half*)(g_scratch + xn_o);
    const half* wh = (const half*)(g_scratch + OFF_W3OFF);

    float acc[2][2][4];
    #pragma unroll
    for (int mt = 0; mt < 2; ++mt)
        #pragma unroll
        for (int nt = 0; nt < 2; ++nt)
            #pragma unroll
            for (int r = 0; r < 4; ++r) acc[mt][nt][r] = 0.f;

    int tpx = tid >> 1, tseg = tid & 1;
    int p = tile * 128 + tpx;
    int ph = p / W, pw = p - ph * W;

    uint32_t bs_saddr = (uint32_t)__cvta_generic_to_shared(&Bsh[0][0]);

    uint4 gr[2];
    auto gather_ldg = [&](int s) {
        int k = s >> 3, c0 = (s & 7) << 5;
        int dy = k / 3 - 1, dx = k % 3 - 1;
        int y = ph + dy, x = pw + dx;
        bool valid = (y >= 0 && y < H && x >= 0 && x < W);
        const half* src = xn + ((size_t)(b * H + y) * W + x) * 256 + c0 + tseg * 16;
        #pragma unroll
        for (int i = 0; i < 2; ++i)
            gr[i] = valid ? *(const uint4*)(src + i * 8) : make_uint4(0, 0, 0, 0);
    };
    auto sts_a = [&](int buf) {
        half* dst = &Ash[buf][tpx * 40 + tseg * 16];
        *(uint4*)&dst[0] = gr[0];
        *(uint4*)&dst[8] = gr[1];
    };
    auto cpasync_b = [&](int s, int buf) {
        int k = s >> 3, c0 = (s & 7) << 5;
        if (tid < 128) {
            int o = tid >> 2, seg = tid & 3;
            cp_async16(bs_saddr + (uint32_t)(buf * 2560 + o * 80 + seg * 16),
                       wh + ((size_t)(k * 32 + o) << 8) + c0 + seg * 8);
        }
        asm volatile("cp.async.commit_group;\n");
    };

    gather_ldg(0);
    cpasync_b(0, 0);

    int lg = lane >> 3, lr = lane & 7;

    for (int s = 0; s < 72; ++s) {
        int cb = s & 1;
        sts_a(cb);
        if (s < 71) gather_ldg(s + 1);
        asm volatile("cp.async.wait_group 0;\n");
        __syncthreads();
        if (s < 71) cpasync_b(s + 1, cb ^ 1);

        const half* Ab = Ash[cb];
        const half* Bb = Bsh[cb];
        #pragma unroll
        for (int ks = 0; ks < 2; ++ks) {
            int kb = ks * 16 + (lg >> 1) * 8;
            uint32_t a[2][4];
            #pragma unroll
            for (int mt = 0; mt < 2; ++mt)
                ldsm_x4(a[mt], Ab + (warpM * 32 + mt * 16 + (lg & 1) * 8 + lr) * 40 + kb);
            uint32_t bf[4];
            ldsm_x4(bf, Bb + (warpN * 16 + (lg & 1) * 8 + lr) * 40 + kb);
            mma_f16(acc[0][0], a[0], bf[0], bf[2]);
            mma_f16(acc[1][0], a[1], bf[0], bf[2]);
            mma_f16(acc[0][1], a[0], bf[1], bf[3]);
            mma_f16(acc[1][1], a[1], bf[1], bf[3]);
        }
        __syncthreads();
    }

    // epilogue: [b][px][27]
    int HWl = H * W;
    int pxb = tile * 128 + warpM * 32 + (lane >> 2);
    #pragma unroll
    for (int nt = 0; nt < 2; ++nt) {
        int o = warpN * 16 + nt * 8 + 2 * (lane & 3);
        float bv0 = (o < 27) ? bias[o] : 0.f;
        float bv1 = (o + 1 < 27) ? bias[o + 1] : 0.f;
        #pragma unroll
        for (int mt = 0; mt < 2; ++mt) {
            #pragma unroll
            for (int rr = 0; rr < 2; ++rr) {
                int px = pxb + mt * 16 + rr * 8;
                float v0 = acc[mt][nt][rr * 2 + 0] + bv0;
                float v1 = acc[mt][nt][rr * 2 + 1] + bv1;
                size_t ob = out_o + ((size_t)b * HWl + px) * 27;
                if (o < 27) {
                    if (o >= 18) v0 = 1.f / (1.f + expf(-v0));
                    g_scratch[ob + o] = v0;
                }
                if (o + 1 < 27) {
                    if (o + 1 >= 18) v1 = 1.f / (1.f + expf(-v1));
                    g_scratch[ob + o + 1] = v1;
                }
            }
        }
    }
}

// ---------------------------------------------------------------------------
// Modulated deformable conv: fused bilinear gather (fp16 in, fp32 combine) +
// FP16 MMA with ldmatrix fragments, pipelined, fused per-(b,c) stats.
// Block: 64 px x 256 o, 256 threads (8 warps = 2M x 4N). 72 chunks of 32 c.
// ---------------------------------------------------------------------------
__global__ __launch_bounds__(256) void mdconv_mma_kernel(
    size_t xn_o, int Hi, int Wi,
    size_t off_o, int offH, int offW, int offmul,
    int stride, size_t w3_o,
    size_t y_o, int HWo, int Wo, size_t stat_o)
{
    extern __shared__ char smraw[];
    half*  Ash  = (half*)smraw;               // [2][64*40]
    half*  Bsh  = (half*)(smraw + 10240);     // [2][256*40]
    float* swt9 = (float*)(smraw + 51200);    // [9*256]
    int*   sb9  = (int*)(smraw + 60416);      // [9*256]

    int b = blockIdx.y, tile = blockIdx.x, tid = threadIdx.x;
    int lane = tid & 31, warp = tid >> 5;
    int warpM = warp & 1, warpN = warp >> 1;

    const half* xn = (const half*)(g_scratch + xn_o);
    const half* w3h = (const half*)(g_scratch + w3_o);

    // precompute gather tables for all 9 taps
    for (int it = tid; it < 576; it += 256) {
        int k = it >> 6, p = it & 63;
        int pg = tile * 64 + p;
        int h = pg / Wo, w = pg - h * Wo;
        size_t ob = off_o + ((size_t)(b * offH + h * offmul) * offW + w * offmul) * 27;
        float oy = g_scratch[ob + 2 * k];
        float ox = g_scratch[ob + 2 * k + 1];
        float m  = g_scratch[ob + 18 + k];
        float py  = (float)(h * stride - 1 + k / 3) + oy;
        float pxx = (float)(w * stride - 1 + k % 3) + ox;
        float fy = floorf(py), fx = floorf(pxx);
        int y0 = (int)fy, x0 = (int)fx;
        float wy = py - fy, wx = pxx - fx;
        int y1 = y0 + 1, x1 = x0 + 1;
        float vy0 = (y0 >= 0 && y0 < Hi) ? 1.f : 0.f;
        float vy1 = (y1 >= 0 && y1 < Hi) ? 1.f : 0.f;
        float vx0 = (x0 >= 0 && x0 < Wi) ? 1.f : 0.f;
        float vx1 = (x1 >= 0 && x1 < Wi) ? 1.f : 0.f;
        int y0c = min(max(y0, 0), Hi - 1), y1c = min(max(y1, 0), Hi - 1);
        int x0c = min(max(x0, 0), Wi - 1), x1c = min(max(x1, 0), Wi - 1);
        int kb = k * 256 + p;
        swt9[kb]       = (1.f - wy) * (1.f - wx) * m * vy0 * vx0;
        swt9[kb + 64]  = (1.f - wy) * wx * m * vy0 * vx1;
        swt9[kb + 128] = wy * (1.f - wx) * m * vy1 * vx0;
        swt9[kb + 192] = wy * wx * m * vy1 * vx1;
        sb9[kb]       = ((b * Hi + y0c) * Wi + x0c) * 256;
        sb9[kb + 64]  = ((b * Hi + y0c) * Wi + x1c) * 256;
        sb9[kb + 128] = ((b * Hi + y1c) * Wi + x0c) * 256;
        sb9[kb + 192] = ((b * Hi + y1c) * Wi + x1c) * 256;
    }
    __syncthreads();

    float acc[2][8][4];
    #pragma unroll
    for (int mt = 0; mt < 2; ++mt)
        #pragma unroll
        for (int nt = 0; nt < 8; ++nt)
            #pragma unroll
            for (int r = 0; r < 4; ++r) acc[mt][nt][r] = 0.f;

    int gpx = tid & 63;
    int gcq = tid >> 6;   // 0..3: 8-channel segment

    uint32_t bs_saddr = (uint32_t)__cvta_generic_to_shared(Bsh);

    float gw0, gw1, gw2, gw3;
    uint4 gv[4];

    auto gather_ldg = [&](int s) {
        int kk = s >> 3, c0n = (s & 7) << 5;
        int kb = kk * 256 + gpx;
        gw0 = swt9[kb]; gw1 = swt9[kb + 64]; gw2 = swt9[kb + 128]; gw3 = swt9[kb + 192];
        int b00 = sb9[kb], b01 = sb9[kb + 64], b10 = sb9[kb + 128], b11 = sb9[kb + 192];
        int cofs = c0n + gcq * 8;
        gv[0] = *(const uint4*)(xn + b00 + cofs);
        gv[1] = *(const uint4*)(xn + b01 + cofs);
        gv[2] = *(const uint4*)(xn + b10 + cofs);
        gv[3] = *(const uint4*)(xn + b11 + cofs);
    };
    auto combine_sts = [&](int buf) {
        uint4 outv;
        half2* po = (half2*)&outv;
        #pragma unroll
        for (int j = 0; j < 4; ++j) {
            float2 f00 = __half22float2(((const half2*)&gv[0])[j]);
            float2 f01 = __half22float2(((const half2*)&gv[1])[j]);
            float2 f10 = __half22float2(((const half2*)&gv[2])[j]);
            float2 f11 = __half22float2(((const half2*)&gv[3])[j]);
            float rx = gw0 * f00.x + gw1 * f01.x + gw2 * f10.x + gw3 * f11.x;
            float ry = gw0 * f00.y + gw1 * f01.y + gw2 * f10.y + gw3 * f11.y;
            po[j] = __floats2half2_rn(rx, ry);
        }
        *(uint4*)&Ash[buf * 2560 + gpx * 40 + gcq * 8] = outv;
    };
    auto cpasync_b = [&](int s, int buf) {
        int kk = s >> 3, c0n = (s & 7) << 5;
        const half* wsrc = w3h + ((size_t)kk << 16) + c0n;   // [k][o][c], row = 256 halves
        #pragma unroll
        for (int it = 0; it < 4; ++it) {
            int e = it * 256 + tid;
            int o = e >> 2, seg = e & 3;
            cp_async16(bs_saddr + (uint32_t)(buf * 20480 + o * 80 + seg * 16),
                       wsrc + o * 256 + seg * 8);
        }
        asm volatile("cp.async.commit_group;\n");
    };

    gather_ldg(0);
    cpasync_b(0, 0);

    int lg = lane >> 3, lr = lane & 7;

    for (int s = 0; s < 72; ++s) {
        int cb = s & 1;
        combine_sts(cb);
        if (s < 71) gather_ldg(s + 1);
        asm volatile("cp.async.wait_group 0;\n");
        __syncthreads();
        if (s < 71) cpasync_b(s + 1, cb ^ 1);

        const half* Ab = Ash + cb * 2560;
        const half* Bb = Bsh + cb * 10240;
        #pragma unroll
        for (int ks = 0; ks < 2; ++ks) {
            int kb = ks * 16 + (lg >> 1) * 8;
            uint32_t a[2][4];
            #pragma unroll
            for (int mt = 0; mt < 2; ++mt)
                ldsm_x4(a[mt], Ab + (warpM * 32 + mt * 16 + (lg & 1) * 8 + lr) * 40 + kb);
            #pragma unroll
            for (int j = 0; j < 4; ++j) {
                uint32_t bf[4];
                ldsm_x4(bf, Bb + (warpN * 64 + j * 16 + (lg & 1) * 8 + lr) * 40 + kb);
                mma_f16(acc[0][2 * j],     a[0], bf[0], bf[2]);
                mma_f16(acc[1][2 * j],     a[1], bf[0], bf[2]);
                mma_f16(acc[0][2 * j + 1], a[0], bf[1], bf[3]);
                mma_f16(acc[1][2 * j + 1], a[1], bf[1], bf[3]);
            }
        }
        __syncthreads();
    }

    // epilogue: Y [b][o][HWo] + fused stats
    float* yp = g_scratch + y_o + (size_t)b * 256 * HWo;
    float* st_sum = g_scratch + stat_o + b * 256;
    float* st_sq  = g_scratch + stat_o + 512 + b * 256;
    int px0 = tile * 64 + warpM * 32 + (lane >> 2);
    #pragma unroll
    for (int nt = 0; nt < 8; ++nt) {
        int o = warpN * 64 + nt * 8 + 2 * (lane & 3);
        float s0 = 0.f, s1 = 0.f, q0 = 0.f, q1 = 0.f;
        #pragma unroll
        for (int mt = 0; mt < 2; ++mt) {
            int px = px0 + mt * 16;
            float v0 = acc[mt][nt][0], v1 = acc[mt][nt][1];
            float v2 = acc[mt][nt][2], v3 = acc[mt][nt][3];
            yp[(size_t)o * HWo + px]           = v0;
            yp[(size_t)(o + 1) * HWo + px]     = v1;
            yp[(size_t)o * HWo + px + 8]       = v2;
            yp[(size_t)(o + 1) * HWo + px + 8] = v3;
            s0 += v0 + v2; s1 += v1 + v3;
            q0 += v0 * v0 + v2 * v2; q1 += v1 * v1 + v3 * v3;
        }
        #pragma unroll
        for (int off = 16; off >= 4; off >>= 1) {
            s0 += __shfl_down_sync(0xffffffffu, s0, off);
            s1 += __shfl_down_sync(0xffffffffu, s1, off);
            q0 += __shfl_down_sync(0xffffffffu, q0, off);
            q1 += __shfl_down_sync(0xffffffffu, q1, off);
        }
        if (lane < 4) {
            atomicAdd(&st_sum[o], s0);
            atomicAdd(&st_sum[o + 1], s1);
            atomicAdd(&st_sq[o], q0);
            atomicAdd(&st_sq[o + 1], q1);
        }
    }
}

// ---------------------------------------------------------------------------
// GN finalize + scale-attn scalar (analytic pooled value).
// ---------------------------------------------------------------------------
__global__ void gn_finalize_kernel(
    size_t sum_o, size_t sq_o,
    const float* __restrict__ gamma, const float* __restrict__ beta,
    const float* __restrict__ w_sa, const float* __restrict__ b_sa,
    float inv_hw, float inv_cnt,
    size_t gnm_o, size_t gnr_o, size_t sv_o)
{
    int b = blockIdx.x, t = threadIdx.x;  // 256
    __shared__ float ss[256], qq[256], gm[16], gr[16], red[256];
    ss[t] = g_scratch[sum_o + b * 256 + t];
    qq[t] = g_scratch[sq_o + b * 256 + t];
    __syncthreads();
    if (t < 16) {
        float S = 0.f, Q = 0.f;
        #pragma unroll
        for (int j = 0; j < 16; ++j) { S += ss[t * 16 + j]; Q += qq[t * 16 + j]; }
        float mean = S * inv_cnt;
        float var = Q * inv_cnt - mean * mean;
        float r = rsqrtf(var + 1e-5f);
        gm[t] = mean; gr[t] = r;
        g_scratch[gnm_o + b * 16 + t] = mean;
        g_scratch[gnr_o + b * 16 + t] = r;
    }
    __syncthreads();
    int g = t >> 4;
    float p = gamma[t] * (ss[t] * inv_hw - gm[g]) * gr[g] + beta[t];
    red[t] = p * w_sa[t];
    __syncthreads();
    for (int off = 128; off; off >>= 1) {
        if (t < off) red[t] += red[t + off];
        __syncthreads();
    }
    if (t == 0) {
        float x = fmaxf(red[0] + b_sa[0], 0.f);
        g_scratch[sv_o + b] = fminf(x + 3.f, 6.f) * (1.f / 6.f);
    }
}

__global__ void zero_kernel(size_t o, int n) {
    int i = blockIdx.x * 256 + threadIdx.x;
    if (i < n) g_scratch[o + i] = 0.f;
}

// ---------------------------------------------------------------------------
// Combine branches + pooled sums.
// ---------------------------------------------------------------------------
__global__ void combine_kernel(
    size_t ymid_o, size_t ylow_o, size_t yhigh_o,
    int hasLow, int hasHigh, int W, int HW, int Hh, int Wh, float ry, float rx,
    size_t gnm_o, size_t gnr_o, size_t sv_o,
    const float* __restrict__ gw_mid, const float* __restrict__ gb_mid,
    const float* __restrict__ gw_low, const float* __restrict__ gb_low,
    const float* __restrict__ gw_high, const float* __restrict__ gb_high,
    float inv_n, size_t sumf_o, size_t p2_o)
{
    int b = blockIdx.z, c = blockIdx.y;
    int px = blockIdx.x * 256 + threadIdx.x;
    int g = c >> 4;
    int gi = b * 16 + g;
    size_t base = ((size_t)(b * 256 + c)) * HW;

    float v = g_scratch[sv_o + b] *
              (gw_mid[c] * (g_scratch[ymid_o + base + px] - g_scratch[gnm_o + gi]) * g_scratch[gnr_o + gi] + gb_mid[c]);
    if (hasLow)
        v += g_scratch[sv_o + 2 + b] *
             (gw_low[c] * (g_scratch[ylow_o + base + px] - g_scratch[gnm_o + 32 + gi]) * g_scratch[gnr_o + 32 + gi] + gb_low[c]);
    if (hasHigh) {
        int h = px / W, w = px - h * W;
        float sy = h * ry, sx = w * rx;
        int yl = (int)sy; int yh2 = min(yl + 1, Hh - 1);
        int xl = (int)sx; int xh = min(xl + 1, Wh - 1);
        float wy = sy - (float)yl, wx = sx - (float)xl;
        const float* hp = g_scratch + yhigh_o + ((size_t)(b * 256 + c)) * Hh * Wh;
        float t0 = hp[yl * Wh + xl] * (1.f - wx) + hp[yl * Wh + xh] * wx;
        float t1 = hp[yh2 * Wh + xl] * (1.f - wx) + hp[yh2 * Wh + xh] * wx;
        float raw = t0 * (1.f - wy) + t1 * wy;
        v += g_scratch[sv_o + 4 + b] *
             (gw_high[c] * (raw - g_scratch[gnm_o + 64 + gi]) * g_scratch[gnr_o + 64 + gi] + gb_high[c]);
    }
    v *= inv_n;
    g_scratch[sumf_o + base + px] = v;

    float r = v;
    #pragma unroll
    for (int o = 16; o; o >>= 1) r += __shfl_down_sync(0xffffffffu, r, o);
    __shared__ float wsum[8];
    if ((threadIdx.x & 31) == 0) wsum[threadIdx.x >> 5] = r;
    __syncthreads();
    if (threadIdx.x == 0) {
        float tt = 0.f;
        #pragma unroll
        for (int i = 0; i < 8; ++i) tt += wsum[i];
        atomicAdd(&g_scratch[p2_o + b * 256 + c], tt);
    }
}

// ---------------------------------------------------------------------------
// DyReLU coefficients.
// ---------------------------------------------------------------------------
__global__ void dycoef_kernel(size_t p2_o, float inv_hw,
    const float* __restrict__ w1, const float* __restrict__ b1,
    const float* __restrict__ w2, const float* __restrict__ b2,
    size_t coef_o)
{
    int b = blockIdx.x, t = threadIdx.x;  // 1024
    __shared__ float pm[256], hb[64];
    if (t < 256) pm[t] = g_scratch[p2_o + b * 256 + t] * inv_hw;
    __syncthreads();
    if (t < 64) {
        float a = b1[t];
        for (int cx = 0; cx < 256; ++cx) a += pm[cx] * w1[t * 256 + cx];
        hb[t] = fmaxf(a, 0.f);
    }
    __syncthreads();
    float a = b2[t];
    #pragma unroll
    for (int i = 0; i < 64; ++i) a += hb[i] * w2[t * 64 + i];
    float hs = fminf(fmaxf(a + 3.f, 0.f), 6.f) * (1.f / 6.f);
    g_scratch[coef_o + b * 1024 + t] = hs - 0.5f;
}

// ---------------------------------------------------------------------------
// Apply DyReLU, write final output.
// ---------------------------------------------------------------------------
__global__ void dyrelu_kernel(size_t sumf_o, size_t coef_o, int HW, float* __restrict__ outp, int CHW) {
    int idx = blockIdx.x * 256 + threadIdx.x;
    int b = idx / CHW;
    int c = (idx - b * CHW) / HW;
    const float* cf = g_scratch + coef_o + b * 1024;
    float x = g_scratch[sumf_o + idx];
    float a1 = cf[c] * 2.f + 1.f, bb1 = cf[256 + c];
    float a2 = cf[512 + c] * 2.f, bb2 = cf[768 + c];
    outp[idx] = fmaxf(x * a1 + bb1, x * a2 + bb2);
}

// ---------------------------------------------------------------------------
// Host orchestration
// ---------------------------------------------------------------------------
extern "C" void kernel_launch(void* const* d_in, const int* in_sizes, int n_in,
                              void* d_out, int out_size) {
    (void)in_sizes; (void)n_in; (void)out_size;
    const float* x0     = (const float*)d_in[0];
    const float* x1     = (const float*)d_in[1];
    const float* x2     = (const float*)d_in[2];
    const float* w_off  = (const float*)d_in[3];
    const float* b_off  = (const float*)d_in[4];
    const float* w_mid  = (const float*)d_in[5];
    const float* g_mid  = (const float*)d_in[6];
    const float* be_mid = (const float*)d_in[7];
    const float* w_low  = (const float*)d_in[8];
    const float* g_low  = (const float*)d_in[9];
    const float* be_low = (const float*)d_in[10];
    const float* w_high = (const float*)d_in[11];
    const float* g_high = (const float*)d_in[12];
    const float* be_high= (const float*)d_in[13];
    const float* w_sa   = (const float*)d_in[14];
    const float* b_sa   = (const float*)d_in[15];
    const float* w_dy1  = (const float*)d_in[16];
    const float* b_dy1  = (const float*)d_in[17];
    const float* w_dy2  = (const float*)d_in[18];
    const float* b_dy2  = (const float*)d_in[19];
    float* out = (float*)d_out;

    static bool attr_set = false;
    if (!attr_set) {
        cudaFuncSetAttribute(mdconv_mma_kernel,
                             cudaFuncAttributeMaxDynamicSharedMemorySize, MD_SMEM_BYTES);
        attr_set = true;
    }

    dim3 tblk(32, 8);
    const int Hs[3] = {128, 64, 32};
    const size_t xn_offs[3] = {OFF_X0N, OFF_X1N, OFF_X2N};

    // Launch order: slot 4 = mdconv mid L0 for the ncu window.
    transpose_kernel<<<dim3(128 * 128 / 32, 8, 2), tblk>>>(x0, OFF_X0N, 128 * 128);   // 1
    prep_kernel<<<2604, 256>>>(w_mid, w_off);                                          // 2
    offconv_mma_kernel<<<dim3(128 * 128 / 128, 2), 256>>>(OFF_X0N, 128, 128, b_off, OFF_OFFB); // 3
    mdconv_mma_kernel<<<dim3(128 * 128 / 64, 2), 256, MD_SMEM_BYTES>>>(                // 4
        OFF_X0N, 128, 128, OFF_OFFB, 128, 128, 1, 1, OFF_W3MID, OFF_YMID, 128 * 128, 128, OFF_STAT);
    reorder_w_half_kernel<<<2304, 256>>>(w_low,  OFF_W3LOW);                           // 5
    reorder_w_half_kernel<<<2304, 256>>>(w_high, OFF_W3HIGH);                          // 6
    transpose_kernel<<<dim3(64 * 64 / 32, 8, 2), tblk>>>(x1, OFF_X1N, 64 * 64);        // 7
    transpose_kernel<<<dim3(32 * 32 / 32, 8, 2), tblk>>>(x2, OFF_X2N, 32 * 32);        // 8

    size_t outoff = 0;
    for (int l = 0; l < 3; ++l) {
        int H = Hs[l], HW = H * H;
        int hasLow = (l > 0), hasHigh = (l < 2);
        int nbr = 1 + hasLow + hasHigh;
        int Hh = H / 2, HWh = Hh * Hh;

        if (l > 0) {
            zero_kernel<<<12, 256>>>(OFF_STAT, 3072);
            offconv_mma_kernel<<<dim3(HW / 128, 2), 256>>>(xn_offs[l], H, H, b_off, OFF_OFFB);
            mdconv_mma_kernel<<<dim3(HW / 64, 2), 256, MD_SMEM_BYTES>>>(
                xn_offs[l], H, H, OFF_OFFB, H, H, 1, 1, OFF_W3MID, OFF_YMID, HW, H, OFF_STAT);
        }
        gn_finalize_kernel<<<2, 256>>>(OFF_STAT, OFF_STAT + 512, g_mid, be_mid, w_sa, b_sa,
                                       1.f / HW, 1.f / (16.f * HW),
                                       OFF_GNM, OFF_GNR, OFF_SV);
        if (hasLow) {
            int Hi = Hs[l - 1];
            mdconv_mma_kernel<<<dim3(HW / 64, 2), 256, MD_SMEM_BYTES>>>(
                xn_offs[l - 1], Hi, Hi, OFF_OFFB, H, H, 1, 2, OFF_W3LOW, OFF_YLOW, HW, H,
                OFF_STAT + 1024);
            gn_finalize_kernel<<<2, 256>>>(OFF_STAT + 1024, OFF_STAT + 1536, g_low, be_low, w_sa, b_sa,
                                           1.f / HW, 1.f / (16.f * HW),
                                           OFF_GNM + 32, OFF_GNR + 32, OFF_SV + 2);
        }
        if (hasHigh) {
            mdconv_mma_kernel<<<dim3(HWh / 64, 2), 256, MD_SMEM_BYTES>>>(
                xn_offs[l + 1], Hh, Hh, OFF_OFFB, H, H, 2, 1, OFF_W3HIGH, OFF_YHIGH, HWh, Hh,
                OFF_STAT + 2048);
            gn_finalize_kernel<<<2, 256>>>(OFF_STAT + 2048, OFF_STAT + 2560, g_high, be_high, w_sa, b_sa,
                                           1.f / HWh, 1.f / (16.f * HWh),
                                           OFF_GNM + 64, OFF_GNR + 64, OFF_SV + 4);
        }

        zero_kernel<<<2, 256>>>(OFF_P2, 512);
        float ry = (float)(Hh - 1) / (float)(H - 1);
        combine_kernel<<<dim3(HW / 256, 256, 2), 256>>>(
            OFF_YMID, OFF_YLOW, OFF_YHIGH, hasLow, hasHigh,
            H, HW, Hh, Hh, ry, ry,
            OFF_GNM, OFF_GNR, OFF_SV,
            g_mid, be_mid, g_low, be_low, g_high, be_high,
            1.f / (float)nbr, OFF_SUMF, OFF_P2);

        dycoef_kernel<<<2, 1024>>>(OFF_P2, 1.f / HW, w_dy1, b_dy1, w_dy2, b_dy2, OFF_COEF);

        int total = 2 * 256 * HW;
        dyrelu_kernel<<<total / 256, 256>>>(OFF_SUMF, OFF_COEF, HW, out + outoff, 256 * HW);
        outoff += (size_t)total;
    }
}